// round 1
// baseline (speedup 1.0000x reference)
#include <cuda_runtime.h>
#include <cuda_bf16.h>
#include <mma.h>
#include <type_traits>

using namespace nvcuda;

// ---------------- problem constants ----------------
#define SEQ    1024
#define BATCH  2
#define TOK    2048          // BATCH*SEQ
#define DIM    1024
#define HEADS  16
#define DHEAD  64
#define QKV3   3072
#define FF     4096
#define FF2X   8192
#define DEPTH  4
#define ATTN_SCALE 0.125f    // 64^-0.5

// ---------------- device scratch (no runtime alloc allowed) ----------------
__device__ __align__(128) __nv_bfloat16 g_wqkv[(long)DEPTH * DIM * QKV3];
__device__ __align__(128) __nv_bfloat16 g_wout[(long)DEPTH * DIM * DIM];
__device__ __align__(128) __nv_bfloat16 g_wff1[(long)DEPTH * DIM * FF2X];
__device__ __align__(128) __nv_bfloat16 g_wff2[(long)DEPTH * FF * DIM];
__device__ __align__(128) __nv_bfloat16 g_h   [(long)TOK * DIM];
__device__ __align__(128) __nv_bfloat16 g_qkv [(long)TOK * QKV3];
__device__ __align__(128) float         g_sc  [32L * 1024 * 1024];
__device__ __align__(128) __nv_bfloat16 g_pr  [32L * 1024 * 1024];
__device__ __align__(128) __nv_bfloat16 g_o   [(long)TOK * DIM];
__device__ __align__(128) __nv_bfloat16 g_u   [(long)TOK * FF2X];
__device__ __align__(128) __nv_bfloat16 g_ff  [(long)TOK * FF];

// ---------------- elementwise kernels ----------------
__global__ void convert_kernel(const float4* __restrict__ src,
                               __nv_bfloat16* __restrict__ dst, long n4) {
    long i = (long)blockIdx.x * blockDim.x + threadIdx.x;
    long stride = (long)gridDim.x * blockDim.x;
    __nv_bfloat162* d2 = reinterpret_cast<__nv_bfloat162*>(dst);
    for (; i < n4; i += stride) {
        float4 v = src[i];
        d2[2 * i]     = __floats2bfloat162_rn(v.x, v.y);
        d2[2 * i + 1] = __floats2bfloat162_rn(v.z, v.w);
    }
}

__global__ void copy_kernel(const float4* __restrict__ src, float4* __restrict__ dst) {
    long i = (long)blockIdx.x * blockDim.x + threadIdx.x;
    dst[i] = src[i];
}

// one block (256 threads) per row of 1024
__global__ __launch_bounds__(256) void ln_kernel(const float* __restrict__ x,
                                                 const float* __restrict__ w,
                                                 const float* __restrict__ b,
                                                 __nv_bfloat16* __restrict__ out) {
    int row = blockIdx.x;
    int t = threadIdx.x;
    const float4 v = reinterpret_cast<const float4*>(x + (long)row * DIM)[t];
    float s = v.x + v.y + v.z + v.w;
    float q = v.x * v.x + v.y * v.y + v.z * v.z + v.w * v.w;
    __shared__ float rs[8], rq[8];
    #pragma unroll
    for (int o = 16; o; o >>= 1) {
        s += __shfl_xor_sync(0xffffffffu, s, o);
        q += __shfl_xor_sync(0xffffffffu, q, o);
    }
    if ((t & 31) == 0) { rs[t >> 5] = s; rq[t >> 5] = q; }
    __syncthreads();
    float ts = 0.f, tq = 0.f;
    #pragma unroll
    for (int i = 0; i < 8; i++) { ts += rs[i]; tq += rq[i]; }
    float mu = ts * (1.f / DIM);
    float var = tq * (1.f / DIM) - mu * mu;
    float rstd = rsqrtf(var + 1e-5f);
    float4 wv = reinterpret_cast<const float4*>(w)[t];
    float4 bv = reinterpret_cast<const float4*>(b)[t];
    __nv_bfloat162* o2 = reinterpret_cast<__nv_bfloat162*>(out + (long)row * DIM);
    o2[2 * t]     = __floats2bfloat162_rn((v.x - mu) * rstd * wv.x + bv.x,
                                          (v.y - mu) * rstd * wv.y + bv.y);
    o2[2 * t + 1] = __floats2bfloat162_rn((v.z - mu) * rstd * wv.z + bv.z,
                                          (v.w - mu) * rstd * wv.w + bv.w);
}

// one block per score row of 1024; applies ATTN_SCALE inside
__global__ __launch_bounds__(256) void softmax_kernel(const float* __restrict__ s,
                                                      __nv_bfloat16* __restrict__ p) {
    long row = blockIdx.x;
    int t = threadIdx.x;
    const float4 v = reinterpret_cast<const float4*>(s + row * 1024)[t];
    float m = fmaxf(fmaxf(v.x, v.y), fmaxf(v.z, v.w));
    __shared__ float red[8];
    #pragma unroll
    for (int o = 16; o; o >>= 1) m = fmaxf(m, __shfl_xor_sync(0xffffffffu, m, o));
    if ((t & 31) == 0) red[t >> 5] = m;
    __syncthreads();
    float bm = red[0];
    #pragma unroll
    for (int i = 1; i < 8; i++) bm = fmaxf(bm, red[i]);
    float e0 = __expf((v.x - bm) * ATTN_SCALE);
    float e1 = __expf((v.y - bm) * ATTN_SCALE);
    float e2 = __expf((v.z - bm) * ATTN_SCALE);
    float e3 = __expf((v.w - bm) * ATTN_SCALE);
    float su = e0 + e1 + e2 + e3;
    __syncthreads();
    #pragma unroll
    for (int o = 16; o; o >>= 1) su += __shfl_xor_sync(0xffffffffu, su, o);
    if ((t & 31) == 0) red[t >> 5] = su;
    __syncthreads();
    float tot = 0.f;
    #pragma unroll
    for (int i = 0; i < 8; i++) tot += red[i];
    float inv = 1.f / tot;
    __nv_bfloat162* p2 = reinterpret_cast<__nv_bfloat162*>(p + row * 1024);
    p2[2 * t]     = __floats2bfloat162_rn(e0 * inv, e1 * inv);
    p2[2 * t + 1] = __floats2bfloat162_rn(e2 * inv, e3 * inv);
}

// GEGLU: ff[i][j] = a * gelu_exact(g), a = u[i][j], g = u[i][j+FF]
__global__ void geglu_kernel(const __nv_bfloat16* __restrict__ u,
                             __nv_bfloat16* __restrict__ ff) {
    long n2 = (long)TOK * FF / 2;
    long i = (long)blockIdx.x * blockDim.x + threadIdx.x;
    long stride = (long)gridDim.x * blockDim.x;
    for (; i < n2; i += stride) {
        long row = i / (FF / 2);
        int j = (int)(i % (FF / 2));
        __nv_bfloat162 a2 = reinterpret_cast<const __nv_bfloat162*>(u + row * FF2X)[j];
        __nv_bfloat162 g2 = reinterpret_cast<const __nv_bfloat162*>(u + row * FF2X + FF)[j];
        float gx = __bfloat162float(g2.x);
        float gy = __bfloat162float(g2.y);
        float r0 = __bfloat162float(a2.x) * (0.5f * gx * (1.f + erff(gx * 0.70710678118654752f)));
        float r1 = __bfloat162float(a2.y) * (0.5f * gy * (1.f + erff(gy * 0.70710678118654752f)));
        reinterpret_cast<__nv_bfloat162*>(ff)[i] = __floats2bfloat162_rn(r0, r1);
    }
}

// ---------------- generic wmma GEMM ----------------
// C[M,N] = A[M,K] * B   (B row-major [K,N] if !BT, else C = A * B^T with B row-major [N,K])
// EPI: 0 = bf16 store (+optional bias), 1 = fp32 direct store, 2 = fp32 residual += (acc+bias)*ls
// batched via blockIdx.z -> (zb = z>>4, zh = z&15) with per-axis element strides.
template <int BM, int BN, int BK, int WMN, int WNN, bool BT, int EPI>
__global__ __launch_bounds__(256) void gemm_kernel(
    const __nv_bfloat16* __restrict__ A, const __nv_bfloat16* __restrict__ B,
    void* __restrict__ Cv, const float* __restrict__ bias, const float* __restrict__ ls,
    int lda, int ldb, int ldc, int K,
    long aB, long aH, long bB, long bH, long cB, long cH) {
    constexpr int THREADS = 256;
    constexpr int WTM = BM / WMN, WTN = BN / WNN;
    constexpr int FM = WTM / 16, FN = WTN / 16;
    constexpr int PAD = 16;
    constexpr int BSR = BT ? BN : BK;
    constexpr int BSC = BT ? (BK + PAD) : (BN + PAD);

    __shared__ __align__(32) __nv_bfloat16 As[BM][BK + PAD];
    __shared__ __align__(32) __nv_bfloat16 Bs[BSR][BSC];
    __shared__ __align__(32) float stage[8][16][24];

    int tid = threadIdx.x;
    int wid = tid >> 5, lane = tid & 31;
    int wm = wid / WNN, wn = wid % WNN;
    int m0 = blockIdx.y * BM, n0 = blockIdx.x * BN;
    int z = blockIdx.z;
    int zb = z >> 4, zh = z & 15;
    A += (long)zb * aB + (long)zh * aH;
    B += (long)zb * bB + (long)zh * bH;
    long cOff = (long)zb * cB + (long)zh * cH;

    wmma::fragment<wmma::accumulator, 16, 16, 16, float> acc[FM][FN];
    #pragma unroll
    for (int i = 0; i < FM; i++)
        #pragma unroll
        for (int j = 0; j < FN; j++) wmma::fill_fragment(acc[i][j], 0.f);

    using BLay = typename std::conditional<BT, wmma::col_major, wmma::row_major>::type;

    for (int k0 = 0; k0 < K; k0 += BK) {
        #pragma unroll
        for (int i = tid * 4; i < BM * BK; i += THREADS * 4) {
            int r = i / BK, c = i % BK;
            *reinterpret_cast<uint2*>(&As[r][c]) =
                *reinterpret_cast<const uint2*>(&A[(long)(m0 + r) * lda + k0 + c]);
        }
        if (!BT) {
            #pragma unroll
            for (int i = tid * 4; i < BK * BN; i += THREADS * 4) {
                int r = i / BN, c = i % BN;
                *reinterpret_cast<uint2*>(&Bs[r][c]) =
                    *reinterpret_cast<const uint2*>(&B[(long)(k0 + r) * ldb + n0 + c]);
            }
        } else {
            #pragma unroll
            for (int i = tid * 4; i < BN * BK; i += THREADS * 4) {
                int r = i / BK, c = i % BK;
                *reinterpret_cast<uint2*>(&Bs[r][c]) =
                    *reinterpret_cast<const uint2*>(&B[(long)(n0 + r) * ldb + k0 + c]);
            }
        }
        __syncthreads();
        #pragma unroll
        for (int kk = 0; kk < BK; kk += 16) {
            wmma::fragment<wmma::matrix_a, 16, 16, 16, __nv_bfloat16, wmma::row_major> af[FM];
            wmma::fragment<wmma::matrix_b, 16, 16, 16, __nv_bfloat16, BLay> bf[FN];
            #pragma unroll
            for (int i = 0; i < FM; i++)
                wmma::load_matrix_sync(af[i], &As[wm * WTM + i * 16][kk], BK + PAD);
            #pragma unroll
            for (int j = 0; j < FN; j++) {
                if (!BT)
                    wmma::load_matrix_sync(bf[j], &Bs[kk][wn * WTN + j * 16], BN + PAD);
                else
                    wmma::load_matrix_sync(bf[j], &Bs[wn * WTN + j * 16][kk], BK + PAD);
            }
            #pragma unroll
            for (int i = 0; i < FM; i++)
                #pragma unroll
                for (int j = 0; j < FN; j++)
                    wmma::mma_sync(acc[i][j], af[i], bf[j], acc[i][j]);
        }
        __syncthreads();
    }

    if (EPI == 1) {
        float* Cf = reinterpret_cast<float*>(Cv) + cOff;
        #pragma unroll
        for (int i = 0; i < FM; i++)
            #pragma unroll
            for (int j = 0; j < FN; j++)
                wmma::store_matrix_sync(
                    &Cf[(long)(m0 + wm * WTM + i * 16) * ldc + n0 + wn * WTN + j * 16],
                    acc[i][j], ldc, wmma::mem_row_major);
    } else {
        #pragma unroll
        for (int i = 0; i < FM; i++) {
            #pragma unroll
            for (int j = 0; j < FN; j++) {
                wmma::store_matrix_sync(&stage[wid][0][0], acc[i][j], 24, wmma::mem_row_major);
                __syncwarp();
                #pragma unroll
                for (int e = lane; e < 256; e += 32) {
                    int r = e >> 4, c = e & 15;
                    int gm = m0 + wm * WTM + i * 16 + r;
                    int gn = n0 + wn * WTN + j * 16 + c;
                    float v = stage[wid][r][c];
                    if (EPI == 0) {
                        if (bias) v += bias[gn];
                        reinterpret_cast<__nv_bfloat16*>(Cv)[cOff + (long)gm * ldc + gn] =
                            __float2bfloat16(v);
                    } else {  // EPI == 2
                        float* Cf = reinterpret_cast<float*>(Cv);
                        long idx = cOff + (long)gm * ldc + gn;
                        Cf[idx] += (v + bias[gn]) * ls[gn];
                    }
                }
                __syncwarp();
            }
        }
    }
}

// ---------------- host ----------------
static void* symAddr(const void* sym) {
    void* p = nullptr;
    cudaGetSymbolAddress(&p, sym);
    return p;
}

extern "C" void kernel_launch(void* const* d_in, const int* in_sizes, int n_in,
                              void* d_out, int out_size) {
    const float* x    = (const float*)d_in[0];
    const float* ln1w = (const float*)d_in[1];
    const float* ln1b = (const float*)d_in[2];
    const float* wqkv = (const float*)d_in[3];
    const float* wout = (const float*)d_in[4];
    const float* bout = (const float*)d_in[5];
    const float* ls1  = (const float*)d_in[6];
    const float* ln2w = (const float*)d_in[7];
    const float* ln2b = (const float*)d_in[8];
    const float* wff1 = (const float*)d_in[9];
    const float* bff1 = (const float*)d_in[10];
    const float* wff2 = (const float*)d_in[11];
    const float* bff2 = (const float*)d_in[12];
    const float* ls2  = (const float*)d_in[13];
    float* out = (float*)d_out;

    __nv_bfloat16* WQKV = (__nv_bfloat16*)symAddr(g_wqkv);
    __nv_bfloat16* WOUT = (__nv_bfloat16*)symAddr(g_wout);
    __nv_bfloat16* WFF1 = (__nv_bfloat16*)symAddr(g_wff1);
    __nv_bfloat16* WFF2 = (__nv_bfloat16*)symAddr(g_wff2);
    __nv_bfloat16* H    = (__nv_bfloat16*)symAddr(g_h);
    __nv_bfloat16* QKV  = (__nv_bfloat16*)symAddr(g_qkv);
    float*         SC   = (float*)symAddr(g_sc);
    __nv_bfloat16* PR   = (__nv_bfloat16*)symAddr(g_pr);
    __nv_bfloat16* O    = (__nv_bfloat16*)symAddr(g_o);
    __nv_bfloat16* U    = (__nv_bfloat16*)symAddr(g_u);
    __nv_bfloat16* FFB  = (__nv_bfloat16*)symAddr(g_ff);

    // weight conversion fp32 -> bf16 (deterministic, per-launch)
    convert_kernel<<<2048, 256>>>((const float4*)wqkv, WQKV, (long)DEPTH * DIM * QKV3 / 4);
    convert_kernel<<<2048, 256>>>((const float4*)wout, WOUT, (long)DEPTH * DIM * DIM / 4);
    convert_kernel<<<2048, 256>>>((const float4*)wff1, WFF1, (long)DEPTH * DIM * FF2X / 4);
    convert_kernel<<<2048, 256>>>((const float4*)wff2, WFF2, (long)DEPTH * FF * DIM / 4);

    // residual stream lives in d_out (fp32)
    copy_kernel<<<2048, 256>>>((const float4*)x, (float4*)out);

    for (int l = 0; l < DEPTH; l++) {
        const __nv_bfloat16* Wq = WQKV + (long)l * DIM * QKV3;
        const __nv_bfloat16* Wo = WOUT + (long)l * DIM * DIM;
        const __nv_bfloat16* W1 = WFF1 + (long)l * DIM * FF2X;
        const __nv_bfloat16* W2 = WFF2 + (long)l * FF * DIM;

        // LN1
        ln_kernel<<<TOK, 256>>>(out, ln1w + l * DIM, ln1b + l * DIM, H);

        // QKV = H @ Wq   [2048 x 3072], K=1024
        gemm_kernel<128, 128, 32, 2, 4, false, 0><<<dim3(24, 16, 1), 256>>>(
            H, Wq, QKV, nullptr, nullptr, DIM, QKV3, QKV3, DIM, 0, 0, 0, 0, 0, 0);

        // scores = Q @ K^T per (b,h): [1024 x 1024], K=64  (fp32 out)
        gemm_kernel<128, 128, 32, 2, 4, true, 1><<<dim3(8, 8, 32), 256>>>(
            QKV, QKV + DIM, SC, nullptr, nullptr, QKV3, QKV3, 1024, DHEAD,
            (long)SEQ * QKV3, (long)DHEAD,
            (long)SEQ * QKV3, (long)DHEAD,
            (long)HEADS * SEQ * SEQ, (long)SEQ * SEQ);

        // softmax rows (scale folded in), fp32 -> bf16 probs
        softmax_kernel<<<32768, 256>>>(SC, PR);

        // O = P @ V per (b,h): [1024 x 64], K=1024
        gemm_kernel<128, 64, 32, 4, 2, false, 0><<<dim3(1, 8, 32), 256>>>(
            PR, QKV + 2 * DIM, O, nullptr, nullptr, SEQ, QKV3, DIM, SEQ,
            (long)HEADS * SEQ * SEQ, (long)SEQ * SEQ,
            (long)SEQ * QKV3, (long)DHEAD,
            (long)SEQ * DIM, (long)DHEAD);

        // out-proj + bias + LayerScale + residual:  out += (O@Wo + bout)*ls1
        gemm_kernel<128, 128, 32, 2, 4, false, 2><<<dim3(8, 16, 1), 256>>>(
            O, Wo, out, bout + l * DIM, ls1 + l * DIM, DIM, DIM, DIM, DIM,
            0, 0, 0, 0, 0, 0);

        // LN2
        ln_kernel<<<TOK, 256>>>(out, ln2w + l * DIM, ln2b + l * DIM, H);

        // U = H @ W1 + bff1  [2048 x 8192], K=1024
        gemm_kernel<128, 128, 32, 2, 4, false, 0><<<dim3(64, 16, 1), 256>>>(
            H, W1, U, bff1 + l * FF2X, nullptr, DIM, FF2X, FF2X, DIM, 0, 0, 0, 0, 0, 0);

        // GEGLU
        geglu_kernel<<<4096, 256>>>(U, FFB);

        // out += (FF @ W2 + bff2)*ls2   [2048 x 1024], K=4096
        gemm_kernel<128, 128, 32, 2, 4, false, 2><<<dim3(8, 16, 1), 256>>>(
            FFB, W2, out, bff2 + l * DIM, ls2 + l * DIM, FF, DIM, DIM, FF,
            0, 0, 0, 0, 0, 0);
    }
}

// round 3
// speedup vs baseline: 1.6747x; 1.6747x over previous
#include <cuda_runtime.h>
#include <cuda_bf16.h>
#include <mma.h>
#include <cstdint>

using namespace nvcuda;

// Feature gate: tcgen05 only exists in the arch-specific (sm_103a/sm_100a) pass.
#if defined(__CUDA_ARCH_FEAT_SM103_ALL) || defined(__CUDA_ARCH_FEAT_SM100_ALL)
#define HAS_TC 1
#else
#define HAS_TC 0
#endif

// ---------------- problem constants ----------------
#define SEQ    1024
#define BATCH  2
#define TOK    2048
#define DIM    1024
#define HEADS  16
#define DHEAD  64
#define QKV3   3072
#define FF     4096
#define FF2X   8192
#define DEPTH  4
#define ATTN_SCALE 0.125f

// ---------------- device scratch ----------------
__device__ __align__(128) __nv_bfloat16 g_wqkvT[(long)DEPTH * QKV3 * DIM];
__device__ __align__(128) __nv_bfloat16 g_woutT[(long)DEPTH * DIM * DIM];
__device__ __align__(128) __nv_bfloat16 g_wff1T[(long)DEPTH * FF2X * DIM];
__device__ __align__(128) __nv_bfloat16 g_wff2T[(long)DEPTH * DIM * FF];
__device__ __align__(128) __nv_bfloat16 g_h   [(long)TOK * DIM];
__device__ __align__(128) __nv_bfloat16 g_qkv [(long)TOK * QKV3];
__device__ __align__(128) __nv_bfloat16 g_vt  [(long)BATCH * HEADS * DHEAD * SEQ];
__device__ __align__(128) float         g_sc  [(long)BATCH * HEADS * SEQ * SEQ];
__device__ __align__(128) __nv_bfloat16 g_pr  [(long)BATCH * HEADS * SEQ * SEQ];
__device__ __align__(128) __nv_bfloat16 g_o   [(long)TOK * DIM];
__device__ __align__(128) __nv_bfloat16 g_u   [(long)TOK * FF2X];
__device__ __align__(128) __nv_bfloat16 g_ff  [(long)TOK * FF];

// ---------------- PTX helpers (arch-gated) ----------------
#if HAS_TC
__device__ __forceinline__ uint32_t smem_u32(const void* p) {
    uint32_t a;
    asm("{ .reg .u64 t; cvta.to.shared.u64 t, %1; cvt.u32.u64 %0, t; }" : "=r"(a) : "l"(p));
    return a;
}
__device__ __forceinline__ uint32_t elect_one() {
    uint32_t p;
    asm volatile("{\n\t.reg .pred p;\n\telect.sync _|p, 0xFFFFFFFF;\n\tselp.b32 %0, 1, 0, p;\n\t}" : "=r"(p));
    return p;
}
#define SWZ(off) ((off) ^ (((off) >> 3) & 0x70))

static constexpr uint64_t DESC_BASE_SW128 =
    (uint64_t(2) << 61) | (uint64_t(1) << 46) | (uint64_t(64) << 32) | (uint64_t(1) << 16);
__device__ __forceinline__ uint64_t make_desc(uint32_t addr) {
    return DESC_BASE_SW128 | ((uint64_t)(addr >> 4) & 0x3FFF);
}
__device__ __forceinline__ void tc_alloc(uint32_t smem_dst, uint32_t ncols) {
    asm volatile("tcgen05.alloc.cta_group::1.sync.aligned.shared::cta.b32 [%0], %1;"
                 :: "r"(smem_dst), "r"(ncols) : "memory");
}
__device__ __forceinline__ void tc_dealloc(uint32_t tmem, uint32_t ncols) {
    asm volatile("tcgen05.dealloc.cta_group::1.sync.aligned.b32 %0, %1;" :: "r"(tmem), "r"(ncols));
}
__device__ __forceinline__ void tc_relinq() {
    asm volatile("tcgen05.relinquish_alloc_permit.cta_group::1.sync.aligned;");
}
__device__ __forceinline__ void tc_mma_f16_ss(uint32_t d, uint64_t ad, uint64_t bd,
                                              uint32_t idesc, uint32_t en) {
    asm volatile(
        "{\n\t.reg .pred p;\n\tsetp.ne.u32 p, %5, 0;\n\t"
        "tcgen05.mma.cta_group::1.kind::f16 [%0], %1, %2, %3, {%4, %4, %4, %4}, p;\n\t}"
        :: "r"(d), "l"(ad), "l"(bd), "r"(idesc), "r"(0u), "r"(en) : "memory");
}
__device__ __forceinline__ void tc_commit(uint32_t mbar) {
    asm volatile("tcgen05.commit.cta_group::1.mbarrier::arrive::one.shared::cluster.b64 [%0];"
                 :: "r"(mbar) : "memory");
}
__device__ __forceinline__ void mbar_init(uint32_t mbar, uint32_t cnt) {
    asm volatile("mbarrier.init.shared.b64 [%0], %1;" :: "r"(mbar), "r"(cnt) : "memory");
}
__device__ __forceinline__ void mbar_wait(uint32_t mbar, uint32_t parity) {
    asm volatile(
        "{\n\t.reg .pred P;\n\t"
        "W_%=:\n\t"
        "mbarrier.try_wait.parity.acquire.cta.shared::cta.b64 P, [%0], %1, 0x989680;\n\t"
        "@P bra.uni D_%=;\n\t"
        "bra.uni W_%=;\n\t"
        "D_%=:\n\t}"
        :: "r"(mbar), "r"(parity) : "memory");
}
#define TC_LD_X32(r, addr) \
    asm volatile("tcgen05.ld.sync.aligned.32x32b.x32.b32 " \
        "{%0,%1,%2,%3,%4,%5,%6,%7,%8,%9,%10,%11,%12,%13,%14,%15," \
        "%16,%17,%18,%19,%20,%21,%22,%23,%24,%25,%26,%27,%28,%29,%30,%31}, [%32];" \
        : "=r"((r)[0]),"=r"((r)[1]),"=r"((r)[2]),"=r"((r)[3]),"=r"((r)[4]),"=r"((r)[5]), \
          "=r"((r)[6]),"=r"((r)[7]),"=r"((r)[8]),"=r"((r)[9]),"=r"((r)[10]),"=r"((r)[11]), \
          "=r"((r)[12]),"=r"((r)[13]),"=r"((r)[14]),"=r"((r)[15]),"=r"((r)[16]),"=r"((r)[17]), \
          "=r"((r)[18]),"=r"((r)[19]),"=r"((r)[20]),"=r"((r)[21]),"=r"((r)[22]),"=r"((r)[23]), \
          "=r"((r)[24]),"=r"((r)[25]),"=r"((r)[26]),"=r"((r)[27]),"=r"((r)[28]),"=r"((r)[29]), \
          "=r"((r)[30]),"=r"((r)[31]) : "r"(addr))
__device__ __forceinline__ void tc_wait_ld()  { asm volatile("tcgen05.wait::ld.sync.aligned;" ::: "memory"); }
__device__ __forceinline__ void fence_after() { asm volatile("tcgen05.fence::after_thread_sync;" ::: "memory"); }
__device__ __forceinline__ void fence_async_smem() { asm volatile("fence.proxy.async.shared::cta;" ::: "memory"); }

template <int ROWS>
__device__ __forceinline__ void stage_tile(uint32_t dst, const __nv_bfloat16* g, int ld) {
    #pragma unroll
    for (int it = 0; it < ROWS * 8 / 256; it++) {
        int s = threadIdx.x + it * 256;
        int r = s >> 3, j = s & 7;
        uint32_t d = dst + SWZ(r * 128 + j * 16);
        const void* p = g + (long)r * ld + j * 8;
        asm volatile("cp.async.cg.shared.global [%0], [%1], 16;" :: "r"(d), "l"(p));
    }
}
#endif  // HAS_TC

// ---------------- unified GEMM kernel ----------------
// C[M,N] = A[M,K] @ B[N,K]^T, A/B bf16 K-major.
// EPI: 0 = bf16 store (+opt bias), 1 = fp32 store, 2 = fp32 residual += (acc+bias)*ls
// Body = tcgen05 on the sm_103a pass, wmma fallback on the portable pass.
template <int BM, int BN, int EPI>
__global__ void __launch_bounds__(256) tc_gemm(
    const __nv_bfloat16* __restrict__ A, const __nv_bfloat16* __restrict__ B,
    void* __restrict__ Cv, const float* __restrict__ bias, const float* __restrict__ ls,
    int lda, int ldb, int ldc, int K,
    long aB, long aH, long bB, long bH, long cB, long cH) {
    extern __shared__ __align__(1024) char smem[];
    const int tid = threadIdx.x;
    const int wid = tid >> 5;

    const int m0 = blockIdx.y * BM, n0 = blockIdx.x * BN;
    const int z = blockIdx.z, zb = z >> 4, zh = z & 15;
    A += (long)zb * aB + (long)zh * aH + (long)m0 * lda;
    B += (long)zb * bB + (long)zh * bH + (long)n0 * ldb;
    const long cOff = (long)zb * cB + (long)zh * cH;

#if HAS_TC
    // ================= tcgen05 path =================
    const uint32_t sb = smem_u32(smem);
    constexpr int ABYTES = BM * 128;
    constexpr int BBYTES = BN * 128;
    constexpr int OFF_A0 = 1024;
    constexpr int OFF_B0 = OFF_A0 + ABYTES;
    constexpr int OFF_A1 = OFF_B0 + BBYTES;
    constexpr int OFF_B1 = OFF_A1 + ABYTES;

    if (wid == 0) { tc_alloc(sb, BN); tc_relinq(); }
    if (tid == 0) { mbar_init(sb + 8, 1); mbar_init(sb + 16, 1); }
    __syncthreads();
    uint32_t tmem;
    asm volatile("ld.shared.b32 %0, [%1];" : "=r"(tmem) : "r"(sb));

    const int nch = K >> 6;
    stage_tile<BM>(sb + OFF_A0, A, lda);
    stage_tile<BN>(sb + OFF_B0, B, ldb);
    asm volatile("cp.async.commit_group;" ::: "memory");
    if (nch > 1) {
        stage_tile<BM>(sb + OFF_A1, A + 64, lda);
        stage_tile<BN>(sb + OFF_B1, B + 64, ldb);
        asm volatile("cp.async.commit_group;" ::: "memory");
    }

    const uint32_t idesc = (1u << 4) | (1u << 7) | (1u << 10) | ((BN / 8) << 17) | ((BM / 16) << 24);
    int ph0 = 0, ph1 = 0;

    for (int c = 0; c < nch; c++) {
        const int bf = c & 1;
        if (c == nch - 1) asm volatile("cp.async.wait_group 0;" ::: "memory");
        else              asm volatile("cp.async.wait_group 1;" ::: "memory");
        __syncthreads();
        if (wid == 0) {
            if (elect_one()) {
                fence_async_smem();
                uint64_t ad = make_desc(sb + (bf ? OFF_A1 : OFF_A0));
                uint64_t bd = make_desc(sb + (bf ? OFF_B1 : OFF_B0));
                #pragma unroll
                for (int kk = 0; kk < 4; kk++)
                    tc_mma_f16_ss(tmem, ad + kk * 2, bd + kk * 2, idesc, (c | kk) != 0);
                tc_commit(sb + 8 + bf * 8);
            }
        }
        if (c + 2 < nch) {
            int& ph = bf ? ph1 : ph0;
            mbar_wait(sb + 8 + bf * 8, ph);
            ph ^= 1;
            stage_tile<BM>(sb + (bf ? OFF_A1 : OFF_A0), A + ((c + 2) << 6), lda);
            stage_tile<BN>(sb + (bf ? OFF_B1 : OFF_B0), B + ((c + 2) << 6), ldb);
            asm volatile("cp.async.commit_group;" ::: "memory");
        }
    }
    {
        const int bf = (nch - 1) & 1;
        mbar_wait(sb + 8 + bf * 8, bf ? ph1 : ph0);
    }
    fence_after();

    if (tid < 128) {
        const int w = wid, l = tid & 31;
        const long row = m0 + w * 32 + l;
        #pragma unroll
        for (int nb = 0; nb < BN; nb += 32) {
            uint32_t r[32];
            TC_LD_X32(r, tmem + nb);
            tc_wait_ld();
            if (EPI == 1) {
                float* Cf = (float*)Cv + cOff + row * ldc + n0 + nb;
                #pragma unroll
                for (int q = 0; q < 8; q++) {
                    float4 v = make_float4(__uint_as_float(r[4 * q]), __uint_as_float(r[4 * q + 1]),
                                           __uint_as_float(r[4 * q + 2]), __uint_as_float(r[4 * q + 3]));
                    *reinterpret_cast<float4*>(Cf + 4 * q) = v;
                }
            } else if (EPI == 0) {
                __nv_bfloat16* Cb = (__nv_bfloat16*)Cv + cOff + row * ldc + n0 + nb;
                #pragma unroll
                for (int q = 0; q < 16; q++) {
                    float a = __uint_as_float(r[2 * q]);
                    float b2 = __uint_as_float(r[2 * q + 1]);
                    if (bias) { a += bias[n0 + nb + 2 * q]; b2 += bias[n0 + nb + 2 * q + 1]; }
                    reinterpret_cast<__nv_bfloat162*>(Cb)[q] = __floats2bfloat162_rn(a, b2);
                }
            } else {
                float* Cf = (float*)Cv + cOff + row * ldc + n0 + nb;
                #pragma unroll
                for (int q = 0; q < 8; q++) {
                    float4 cv = *reinterpret_cast<float4*>(Cf + 4 * q);
                    cv.x += (__uint_as_float(r[4 * q]) + bias[n0 + nb + 4 * q]) * ls[n0 + nb + 4 * q];
                    cv.y += (__uint_as_float(r[4 * q + 1]) + bias[n0 + nb + 4 * q + 1]) * ls[n0 + nb + 4 * q + 1];
                    cv.z += (__uint_as_float(r[4 * q + 2]) + bias[n0 + nb + 4 * q + 2]) * ls[n0 + nb + 4 * q + 2];
                    cv.w += (__uint_as_float(r[4 * q + 3]) + bias[n0 + nb + 4 * q + 3]) * ls[n0 + nb + 4 * q + 3];
                    *reinterpret_cast<float4*>(Cf + 4 * q) = cv;
                }
            }
        }
    }
    __syncthreads();
    if (wid == 0) tc_dealloc(tmem, BN);
#else
    // ================= wmma fallback (portable pass) =================
    constexpr int BK = 32;
    constexpr int PAD = 16;
    constexpr int WNN = (BN == 128) ? 4 : 2;
    constexpr int WMN = 8 / WNN;
    constexpr int WTM = BM / WMN, WTN = BN / WNN;
    constexpr int FM = WTM / 16, FN = WTN / 16;

    __nv_bfloat16* As = reinterpret_cast<__nv_bfloat16*>(smem);            // [BM][BK+PAD]
    __nv_bfloat16* Bs = As + BM * (BK + PAD);                              // [BN][BK+PAD]
    float* stage = reinterpret_cast<float*>(Bs + BN * (BK + PAD));         // [8][16][24]

    const int lane = tid & 31;
    const int wm = wid / WNN, wn = wid % WNN;

    wmma::fragment<wmma::accumulator, 16, 16, 16, float> acc[FM][FN];
    #pragma unroll
    for (int i = 0; i < FM; i++)
        #pragma unroll
        for (int j = 0; j < FN; j++) wmma::fill_fragment(acc[i][j], 0.f);

    for (int k0 = 0; k0 < K; k0 += BK) {
        #pragma unroll
        for (int i = tid * 4; i < BM * BK; i += 256 * 4) {
            int r = i / BK, c = i % BK;
            *reinterpret_cast<uint2*>(&As[r * (BK + PAD) + c]) =
                *reinterpret_cast<const uint2*>(&A[(long)r * lda + k0 + c]);
        }
        #pragma unroll
        for (int i = tid * 4; i < BN * BK; i += 256 * 4) {
            int r = i / BK, c = i % BK;
            *reinterpret_cast<uint2*>(&Bs[r * (BK + PAD) + c]) =
                *reinterpret_cast<const uint2*>(&B[(long)r * ldb + k0 + c]);
        }
        __syncthreads();
        #pragma unroll
        for (int kk = 0; kk < BK; kk += 16) {
            wmma::fragment<wmma::matrix_a, 16, 16, 16, __nv_bfloat16, wmma::row_major> af[FM];
            wmma::fragment<wmma::matrix_b, 16, 16, 16, __nv_bfloat16, wmma::col_major> bf[FN];
            #pragma unroll
            for (int i = 0; i < FM; i++)
                wmma::load_matrix_sync(af[i], &As[(wm * WTM + i * 16) * (BK + PAD) + kk], BK + PAD);
            #pragma unroll
            for (int j = 0; j < FN; j++)
                wmma::load_matrix_sync(bf[j], &Bs[(wn * WTN + j * 16) * (BK + PAD) + kk], BK + PAD);
            #pragma unroll
            for (int i = 0; i < FM; i++)
                #pragma unroll
                for (int j = 0; j < FN; j++)
                    wmma::mma_sync(acc[i][j], af[i], bf[j], acc[i][j]);
        }
        __syncthreads();
    }

    if (EPI == 1) {
        float* Cf = reinterpret_cast<float*>(Cv) + cOff;
        #pragma unroll
        for (int i = 0; i < FM; i++)
            #pragma unroll
            for (int j = 0; j < FN; j++)
                wmma::store_matrix_sync(
                    &Cf[(long)(m0 + wm * WTM + i * 16) * ldc + n0 + wn * WTN + j * 16],
                    acc[i][j], ldc, wmma::mem_row_major);
    } else {
        #pragma unroll
        for (int i = 0; i < FM; i++) {
            #pragma unroll
            for (int j = 0; j < FN; j++) {
                wmma::store_matrix_sync(stage + wid * 384, acc[i][j], 24, wmma::mem_row_major);
                __syncwarp();
                #pragma unroll
                for (int e = lane; e < 256; e += 32) {
                    int r = e >> 4, c = e & 15;
                    int gm = m0 + wm * WTM + i * 16 + r;
                    int gn = n0 + wn * WTN + j * 16 + c;
                    float v = stage[wid * 384 + r * 24 + c];
                    if (EPI == 0) {
                        if (bias) v += bias[gn];
                        reinterpret_cast<__nv_bfloat16*>(Cv)[cOff + (long)gm * ldc + gn] =
                            __float2bfloat16(v);
                    } else {
                        float* Cf = reinterpret_cast<float*>(Cv);
                        long idx = cOff + (long)gm * ldc + gn;
                        Cf[idx] += (v + bias[gn]) * ls[gn];
                    }
                }
                __syncwarp();
            }
        }
    }
#endif
}

// ---------------- elementwise kernels ----------------
__global__ void copy_kernel(const float4* __restrict__ src, float4* __restrict__ dst) {
    long i = (long)blockIdx.x * blockDim.x + threadIdx.x;
    dst[i] = src[i];
}

__global__ __launch_bounds__(256) void convT_kernel(const float* __restrict__ src,
                                                    __nv_bfloat16* __restrict__ dst,
                                                    int K, int N) {
    __shared__ float tile[32][33];
    int d = blockIdx.z;
    src += (long)d * K * N;
    dst += (long)d * K * N;
    int k0 = blockIdx.y * 32, n0 = blockIdx.x * 32;
    #pragma unroll
    for (int i = threadIdx.y; i < 32; i += 8)
        tile[i][threadIdx.x] = src[(long)(k0 + i) * N + n0 + threadIdx.x];
    __syncthreads();
    #pragma unroll
    for (int i = threadIdx.y; i < 32; i += 8)
        dst[(long)(n0 + i) * K + k0 + threadIdx.x] = __float2bfloat16(tile[threadIdx.x][i]);
}

__global__ __launch_bounds__(256) void vT_kernel(const __nv_bfloat16* __restrict__ qkv,
                                                 __nv_bfloat16* __restrict__ vt) {
    __shared__ __nv_bfloat16 tile[32][33];
    int bh = blockIdx.z;
    int b = bh >> 4, h = bh & 15;
    int t0 = blockIdx.x * 32, d0 = blockIdx.y * 32;
    const __nv_bfloat16* src = qkv + (long)(b * SEQ) * QKV3 + 2048 + h * 64;
    #pragma unroll
    for (int i = threadIdx.y; i < 32; i += 8)
        tile[i][threadIdx.x] = src[(long)(t0 + i) * QKV3 + d0 + threadIdx.x];
    __syncthreads();
    __nv_bfloat16* dst = vt + (long)bh * 64 * SEQ;
    #pragma unroll
    for (int i = threadIdx.y; i < 32; i += 8)
        dst[(long)(d0 + i) * SEQ + t0 + threadIdx.x] = tile[threadIdx.x][i];
}

__global__ __launch_bounds__(256) void ln_kernel(const float* __restrict__ x,
                                                 const float* __restrict__ w,
                                                 const float* __restrict__ b,
                                                 __nv_bfloat16* __restrict__ out) {
    int row = blockIdx.x;
    int t = threadIdx.x;
    const float4 v = reinterpret_cast<const float4*>(x + (long)row * DIM)[t];
    float s = v.x + v.y + v.z + v.w;
    float q = v.x * v.x + v.y * v.y + v.z * v.z + v.w * v.w;
    __shared__ float rs[8], rq[8];
    #pragma unroll
    for (int o = 16; o; o >>= 1) {
        s += __shfl_xor_sync(0xffffffffu, s, o);
        q += __shfl_xor_sync(0xffffffffu, q, o);
    }
    if ((t & 31) == 0) { rs[t >> 5] = s; rq[t >> 5] = q; }
    __syncthreads();
    float ts = 0.f, tq = 0.f;
    #pragma unroll
    for (int i = 0; i < 8; i++) { ts += rs[i]; tq += rq[i]; }
    float mu = ts * (1.f / DIM);
    float var = tq * (1.f / DIM) - mu * mu;
    float rstd = rsqrtf(var + 1e-5f);
    float4 wv = reinterpret_cast<const float4*>(w)[t];
    float4 bv = reinterpret_cast<const float4*>(b)[t];
    __nv_bfloat162* o2 = reinterpret_cast<__nv_bfloat162*>(out + (long)row * DIM);
    o2[2 * t]     = __floats2bfloat162_rn((v.x - mu) * rstd * wv.x + bv.x,
                                          (v.y - mu) * rstd * wv.y + bv.y);
    o2[2 * t + 1] = __floats2bfloat162_rn((v.z - mu) * rstd * wv.z + bv.z,
                                          (v.w - mu) * rstd * wv.w + bv.w);
}

__global__ __launch_bounds__(256) void softmax_kernel(const float* __restrict__ s,
                                                      __nv_bfloat16* __restrict__ p) {
    long row = blockIdx.x;
    int t = threadIdx.x;
    const float4 v = reinterpret_cast<const float4*>(s + row * 1024)[t];
    float m = fmaxf(fmaxf(v.x, v.y), fmaxf(v.z, v.w));
    __shared__ float red[8];
    #pragma unroll
    for (int o = 16; o; o >>= 1) m = fmaxf(m, __shfl_xor_sync(0xffffffffu, m, o));
    if ((t & 31) == 0) red[t >> 5] = m;
    __syncthreads();
    float bm = red[0];
    #pragma unroll
    for (int i = 1; i < 8; i++) bm = fmaxf(bm, red[i]);
    float e0 = __expf((v.x - bm) * ATTN_SCALE);
    float e1 = __expf((v.y - bm) * ATTN_SCALE);
    float e2 = __expf((v.z - bm) * ATTN_SCALE);
    float e3 = __expf((v.w - bm) * ATTN_SCALE);
    float su = e0 + e1 + e2 + e3;
    __syncthreads();
    #pragma unroll
    for (int o = 16; o; o >>= 1) su += __shfl_xor_sync(0xffffffffu, su, o);
    if ((t & 31) == 0) red[t >> 5] = su;
    __syncthreads();
    float tot = 0.f;
    #pragma unroll
    for (int i = 0; i < 8; i++) tot += red[i];
    float inv = 1.f / tot;
    __nv_bfloat162* p2 = reinterpret_cast<__nv_bfloat162*>(p + row * 1024);
    p2[2 * t]     = __floats2bfloat162_rn(e0 * inv, e1 * inv);
    p2[2 * t + 1] = __floats2bfloat162_rn(e2 * inv, e3 * inv);
}

__global__ void geglu_kernel(const __nv_bfloat16* __restrict__ u,
                             __nv_bfloat16* __restrict__ ff) {
    long n2 = (long)TOK * FF / 2;
    long i = (long)blockIdx.x * blockDim.x + threadIdx.x;
    long stride = (long)gridDim.x * blockDim.x;
    for (; i < n2; i += stride) {
        long row = i / (FF / 2);
        int j = (int)(i % (FF / 2));
        __nv_bfloat162 a2 = reinterpret_cast<const __nv_bfloat162*>(u + row * FF2X)[j];
        __nv_bfloat162 g2 = reinterpret_cast<const __nv_bfloat162*>(u + row * FF2X + FF)[j];
        float gx = __bfloat162float(g2.x);
        float gy = __bfloat162float(g2.y);
        float r0 = __bfloat162float(a2.x) * (0.5f * gx * (1.f + erff(gx * 0.70710678118654752f)));
        float r1 = __bfloat162float(a2.y) * (0.5f * gy * (1.f + erff(gy * 0.70710678118654752f)));
        reinterpret_cast<__nv_bfloat162*>(ff)[i] = __floats2bfloat162_rn(r0, r1);
    }
}

// ---------------- host ----------------
static void* symAddr(const void* sym) {
    void* p = nullptr;
    cudaGetSymbolAddress(&p, sym);
    return p;
}

extern "C" void kernel_launch(void* const* d_in, const int* in_sizes, int n_in,
                              void* d_out, int out_size) {
    const float* x    = (const float*)d_in[0];
    const float* ln1w = (const float*)d_in[1];
    const float* ln1b = (const float*)d_in[2];
    const float* wqkv = (const float*)d_in[3];
    const float* wout = (const float*)d_in[4];
    const float* bout = (const float*)d_in[5];
    const float* ls1  = (const float*)d_in[6];
    const float* ln2w = (const float*)d_in[7];
    const float* ln2b = (const float*)d_in[8];
    const float* wff1 = (const float*)d_in[9];
    const float* bff1 = (const float*)d_in[10];
    const float* wff2 = (const float*)d_in[11];
    const float* bff2 = (const float*)d_in[12];
    const float* ls2  = (const float*)d_in[13];
    float* out = (float*)d_out;

    __nv_bfloat16* WQ  = (__nv_bfloat16*)symAddr(g_wqkvT);
    __nv_bfloat16* WO  = (__nv_bfloat16*)symAddr(g_woutT);
    __nv_bfloat16* W1  = (__nv_bfloat16*)symAddr(g_wff1T);
    __nv_bfloat16* W2  = (__nv_bfloat16*)symAddr(g_wff2T);
    __nv_bfloat16* H   = (__nv_bfloat16*)symAddr(g_h);
    __nv_bfloat16* QKV = (__nv_bfloat16*)symAddr(g_qkv);
    __nv_bfloat16* VT  = (__nv_bfloat16*)symAddr(g_vt);
    float*         SC  = (float*)symAddr(g_sc);
    __nv_bfloat16* PR  = (__nv_bfloat16*)symAddr(g_pr);
    __nv_bfloat16* O   = (__nv_bfloat16*)symAddr(g_o);
    __nv_bfloat16* U   = (__nv_bfloat16*)symAddr(g_u);
    __nv_bfloat16* FFB = (__nv_bfloat16*)symAddr(g_ff);

    constexpr int SM_128 = 1024 + 2 * (128 * 128 + 128 * 128); // 66560
    constexpr int SM_64  = 1024 + 2 * (128 * 128 + 64 * 128);  // 50176
    cudaFuncSetAttribute(tc_gemm<128, 128, 0>, cudaFuncAttributeMaxDynamicSharedMemorySize, SM_128);
    cudaFuncSetAttribute(tc_gemm<128, 128, 1>, cudaFuncAttributeMaxDynamicSharedMemorySize, SM_128);
    cudaFuncSetAttribute(tc_gemm<128, 128, 2>, cudaFuncAttributeMaxDynamicSharedMemorySize, SM_128);
    cudaFuncSetAttribute(tc_gemm<128, 64, 0>,  cudaFuncAttributeMaxDynamicSharedMemorySize, SM_64);

    convT_kernel<<<dim3(QKV3 / 32, DIM / 32, DEPTH), dim3(32, 8)>>>(wqkv, WQ, DIM, QKV3);
    convT_kernel<<<dim3(DIM / 32, DIM / 32, DEPTH), dim3(32, 8)>>>(wout, WO, DIM, DIM);
    convT_kernel<<<dim3(FF2X / 32, DIM / 32, DEPTH), dim3(32, 8)>>>(wff1, W1, DIM, FF2X);
    convT_kernel<<<dim3(DIM / 32, FF / 32, DEPTH), dim3(32, 8)>>>(wff2, W2, FF, DIM);

    copy_kernel<<<2048, 256>>>((const float4*)x, (float4*)out);

    for (int l = 0; l < DEPTH; l++) {
        const __nv_bfloat16* Wq = WQ + (long)l * DIM * QKV3;
        const __nv_bfloat16* Wo = WO + (long)l * DIM * DIM;
        const __nv_bfloat16* Wf1 = W1 + (long)l * DIM * FF2X;
        const __nv_bfloat16* Wf2 = W2 + (long)l * DIM * FF;

        ln_kernel<<<TOK, 256>>>(out, ln1w + l * DIM, ln1b + l * DIM, H);

        // QKV = H @ WqT^T  [2048 x 3072], K=1024
        tc_gemm<128, 128, 0><<<dim3(24, 16, 1), 256, SM_128>>>(
            H, Wq, QKV, nullptr, nullptr, DIM, DIM, QKV3, DIM, 0, 0, 0, 0, 0, 0);

        vT_kernel<<<dim3(32, 2, 32), dim3(32, 8)>>>(QKV, VT);

        // scores = Q @ K^T per (b,h)  [1024 x 1024], K=64
        tc_gemm<128, 128, 1><<<dim3(8, 8, 32), 256, SM_128>>>(
            QKV, QKV + DIM, SC, nullptr, nullptr, QKV3, QKV3, SEQ, DHEAD,
            (long)SEQ * QKV3, 64L, (long)SEQ * QKV3, 64L,
            (long)HEADS * SEQ * SEQ, (long)SEQ * SEQ);

        softmax_kernel<<<BATCH * HEADS * SEQ, 256>>>(SC, PR);

        // O = P @ VT^T per (b,h)  [1024 x 64], K=1024
        tc_gemm<128, 64, 0><<<dim3(1, 8, 32), 256, SM_64>>>(
            PR, VT, O, nullptr, nullptr, SEQ, SEQ, DIM, SEQ,
            (long)HEADS * SEQ * SEQ, (long)SEQ * SEQ,
            (long)HEADS * DHEAD * SEQ, (long)DHEAD * SEQ,
            (long)SEQ * DIM, 64L);

        // out += (O @ WoT^T + bout) * ls1
        tc_gemm<128, 128, 2><<<dim3(8, 16, 1), 256, SM_128>>>(
            O, Wo, out, bout + l * DIM, ls1 + l * DIM, DIM, DIM, DIM, DIM, 0, 0, 0, 0, 0, 0);

        ln_kernel<<<TOK, 256>>>(out, ln2w + l * DIM, ln2b + l * DIM, H);

        // U = H @ W1T^T + bff1  [2048 x 8192], K=1024
        tc_gemm<128, 128, 0><<<dim3(64, 16, 1), 256, SM_128>>>(
            H, Wf1, U, bff1 + l * FF2X, nullptr, DIM, DIM, FF2X, DIM, 0, 0, 0, 0, 0, 0);

        geglu_kernel<<<4096, 256>>>(U, FFB);

        // out += (FF @ W2T^T + bff2) * ls2  [2048 x 1024], K=4096
        tc_gemm<128, 128, 2><<<dim3(8, 16, 1), 256, SM_128>>>(
            FFB, Wf2, out, bff2 + l * DIM, ls2 + l * DIM, FF, FF, DIM, FF, 0, 0, 0, 0, 0, 0);
    }
}

// round 4
// speedup vs baseline: 2.1277x; 1.2705x over previous
#include <cuda_runtime.h>
#include <cuda_bf16.h>
#include <cstdint>

// ---------------- problem constants ----------------
#define SEQ    1024
#define BATCH  2
#define TOK    2048
#define DIM    1024
#define HEADS  16
#define DHEAD  64
#define QKV3   3072
#define FF     4096
#define FF2X   8192
#define DEPTH  4
#define ATTN_SCALE 0.125f

// ---------------- device scratch ----------------
__device__ __align__(128) __nv_bfloat16 g_wqkv[(long)DEPTH * DIM * QKV3];
__device__ __align__(128) __nv_bfloat16 g_wout[(long)DEPTH * DIM * DIM];
__device__ __align__(128) __nv_bfloat16 g_wff1[(long)DEPTH * DIM * FF2X];
__device__ __align__(128) __nv_bfloat16 g_wff2[(long)DEPTH * FF * DIM];
__device__ __align__(128) __nv_bfloat16 g_h   [(long)TOK * DIM];
__device__ __align__(128) __nv_bfloat16 g_qkv [(long)TOK * QKV3];
__device__ __align__(128) float         g_sc  [(long)BATCH * HEADS * SEQ * SEQ];
__device__ __align__(128) __nv_bfloat16 g_pr  [(long)BATCH * HEADS * SEQ * SEQ];
__device__ __align__(128) __nv_bfloat16 g_o   [(long)TOK * DIM];
__device__ __align__(128) __nv_bfloat16 g_u   [(long)TOK * FF2X];
__device__ __align__(128) __nv_bfloat16 g_ff  [(long)TOK * FF];

// ---------------- helpers ----------------
__device__ __forceinline__ uint32_t smem_u32(const void* p) {
    uint32_t a;
    asm("{ .reg .u64 t; cvta.to.shared.u64 t, %1; cvt.u32.u64 %0, t; }" : "=r"(a) : "l"(p));
    return a;
}
__device__ __forceinline__ void cpasync16(uint32_t dst, const void* src) {
    asm volatile("cp.async.cg.shared.global [%0], [%1], 16;" :: "r"(dst), "l"(src));
}
__device__ __forceinline__ void ldsm_x4(uint32_t* r, uint32_t addr) {
    asm volatile("ldmatrix.sync.aligned.m8n8.x4.shared.b16 {%0,%1,%2,%3}, [%4];"
                 : "=r"(r[0]), "=r"(r[1]), "=r"(r[2]), "=r"(r[3]) : "r"(addr));
}
__device__ __forceinline__ void ldsm_x2t(uint32_t* r, uint32_t addr) {
    asm volatile("ldmatrix.sync.aligned.m8n8.x2.trans.shared.b16 {%0,%1}, [%2];"
                 : "=r"(r[0]), "=r"(r[1]) : "r"(addr));
}
__device__ __forceinline__ void ldsm_x2(uint32_t* r, uint32_t addr) {
    asm volatile("ldmatrix.sync.aligned.m8n8.x2.shared.b16 {%0,%1}, [%2];"
                 : "=r"(r[0]), "=r"(r[1]) : "r"(addr));
}
__device__ __forceinline__ void mma16816(float* c, const uint32_t* a, const uint32_t* b) {
    asm volatile(
        "mma.sync.aligned.m16n8k16.row.col.f32.bf16.bf16.f32 "
        "{%0,%1,%2,%3}, {%4,%5,%6,%7}, {%8,%9}, {%0,%1,%2,%3};"
        : "+f"(c[0]), "+f"(c[1]), "+f"(c[2]), "+f"(c[3])
        : "r"(a[0]), "r"(a[1]), "r"(a[2]), "r"(a[3]), "r"(b[0]), "r"(b[1]));
}

// ---------------- pipelined mma.sync GEMM ----------------
// C[M,N] = A[M,K] @ B.  A bf16 K-major.
// KN=1: B stored [K,N] (row stride ldb).  KN=0: B stored [N,K] (K-major).
// EPI: 0 = bf16 store (+opt bias), 1 = fp32 store, 2 = fp32 residual += (acc+bias)*ls
// batch via blockIdx.z -> (zb = z>>4, zh = z&15).
template <int ROWS, int CPR, int STRIDE>
__device__ __forceinline__ void stage_t(uint32_t dst, const __nv_bfloat16* g, int ld) {
    #pragma unroll
    for (int it = 0; it < ROWS * CPR / 256; it++) {
        int s = threadIdx.x + it * 256;
        int r = s / CPR, j = s % CPR;
        cpasync16(dst + (r * STRIDE + j * 8) * 2, g + (long)r * ld + j * 8);
    }
}

template <int BM, int BN, int KN, int EPI>
__global__ void __launch_bounds__(256, 2) mma_gemm(
    const __nv_bfloat16* __restrict__ A, const __nv_bfloat16* __restrict__ B,
    void* __restrict__ Cv, const float* __restrict__ bias, const float* __restrict__ ls,
    int lda, int ldb, int ldc, int K,
    long aB, long aH, long bB, long bH, long cB, long cH) {
    constexpr int BK = 64;
    constexpr int AST = BK + 8;                 // A smem stride (elems)
    constexpr int BST = KN ? (BN + 8) : (BK + 8);
    constexpr int BROWS = KN ? BK : BN;
    constexpr int ABYTES = BM * AST * 2;
    constexpr int BBYTES = BROWS * BST * 2;
    constexpr int STAGE = ABYTES + BBYTES;

    extern __shared__ __align__(128) char smem[];
    const uint32_t sb = smem_u32(smem);

    const int tid = threadIdx.x;
    const int wid = tid >> 5, l = tid & 31;

    constexpr int WROWS = (BN >= 128) ? 2 : 4;
    constexpr int WCOLS = 8 / WROWS;
    constexpr int WTM = BM / WROWS;
    constexpr int WTN = BN / WCOLS;
    constexpr int FM = WTM / 16;
    constexpr int FN = WTN / 8;
    const int wm = (wid / WCOLS) * WTM;
    const int wn = (wid % WCOLS) * WTN;

    const int m0 = blockIdx.y * BM, n0 = blockIdx.x * BN;
    const int z = blockIdx.z, zb = z >> 4, zh = z & 15;
    A += (long)zb * aB + (long)zh * aH + (long)m0 * lda;
    if (KN) B += (long)zb * bB + (long)zh * bH + n0;
    else    B += (long)zb * bB + (long)zh * bH + (long)n0 * ldb;
    const long cOff = (long)zb * cB + (long)zh * cH;

    const int nch = K >> 6;

    // prologue: stage up to 2 chunks
    {
        stage_t<BM, 8, AST>(sb, A, lda);
        if (KN) stage_t<BK, BN / 8, BST>(sb + ABYTES, B, ldb);
        else    stage_t<BN, 8, BST>(sb + ABYTES, B, ldb);
        asm volatile("cp.async.commit_group;" ::: "memory");
        if (nch > 1) {
            stage_t<BM, 8, AST>(sb + STAGE, A + 64, lda);
            if (KN) stage_t<BK, BN / 8, BST>(sb + STAGE + ABYTES, B + 64L * ldb, ldb);
            else    stage_t<BN, 8, BST>(sb + STAGE + ABYTES, B + 64, ldb);
            asm volatile("cp.async.commit_group;" ::: "memory");
        }
    }

    float acc[FM][FN][4];
    #pragma unroll
    for (int i = 0; i < FM; i++)
        #pragma unroll
        for (int j = 0; j < FN; j++)
            #pragma unroll
            for (int q = 0; q < 4; q++) acc[i][j][q] = 0.f;

    for (int c = 0; c < nch; c++) {
        if (c + 1 < nch) asm volatile("cp.async.wait_group 1;" ::: "memory");
        else             asm volatile("cp.async.wait_group 0;" ::: "memory");
        __syncthreads();

        const uint32_t sA = sb + (c % 3) * STAGE;
        const uint32_t sB = sA + ABYTES;

        #pragma unroll
        for (int kk = 0; kk < 4; kk++) {
            uint32_t af[FM][4], bf[FN][2];
            #pragma unroll
            for (int i = 0; i < FM; i++)
                ldsm_x4(af[i], sA + ((wm + i * 16 + (l & 15)) * AST + kk * 16 + (l >> 4) * 8) * 2);
            #pragma unroll
            for (int j = 0; j < FN; j++) {
                if (KN)
                    ldsm_x2t(bf[j], sB + ((kk * 16 + (l & 15)) * BST + wn + j * 8) * 2);
                else
                    ldsm_x2(bf[j], sB + ((wn + j * 8 + (l & 7)) * BST + kk * 16 + (l >> 3) * 8) * 2);
            }
            #pragma unroll
            for (int i = 0; i < FM; i++)
                #pragma unroll
                for (int j = 0; j < FN; j++)
                    mma16816(acc[i][j], af[i], bf[j]);
        }

        if (c + 2 < nch) {
            const uint32_t dA = sb + ((c + 2) % 3) * STAGE;
            stage_t<BM, 8, AST>(dA, A + (long)(c + 2) * 64, lda);
            if (KN) stage_t<BK, BN / 8, BST>(dA + ABYTES, B + (long)(c + 2) * 64 * ldb, ldb);
            else    stage_t<BN, 8, BST>(dA + ABYTES, B + (long)(c + 2) * 64, ldb);
            asm volatile("cp.async.commit_group;" ::: "memory");
        }
    }

    // -------- epilogue from accumulator registers --------
    const int tr = l >> 2;          // row within 8
    const int tc = (l & 3) * 2;     // col pair
    #pragma unroll
    for (int i = 0; i < FM; i++) {
        #pragma unroll
        for (int j = 0; j < FN; j++) {
            const int gm0 = m0 + wm + i * 16 + tr;
            const int gm1 = gm0 + 8;
            const int gn = n0 + wn + j * 8 + tc;
            if (EPI == 1) {
                float* Cf = (float*)Cv + cOff;
                *reinterpret_cast<float2*>(Cf + (long)gm0 * ldc + gn) =
                    make_float2(acc[i][j][0], acc[i][j][1]);
                *reinterpret_cast<float2*>(Cf + (long)gm1 * ldc + gn) =
                    make_float2(acc[i][j][2], acc[i][j][3]);
            } else if (EPI == 0) {
                __nv_bfloat16* Cb = (__nv_bfloat16*)Cv + cOff;
                float b0 = 0.f, b1 = 0.f;
                if (bias) { b0 = bias[gn]; b1 = bias[gn + 1]; }
                *reinterpret_cast<__nv_bfloat162*>(Cb + (long)gm0 * ldc + gn) =
                    __floats2bfloat162_rn(acc[i][j][0] + b0, acc[i][j][1] + b1);
                *reinterpret_cast<__nv_bfloat162*>(Cb + (long)gm1 * ldc + gn) =
                    __floats2bfloat162_rn(acc[i][j][2] + b0, acc[i][j][3] + b1);
            } else {
                float* Cf = (float*)Cv + cOff;
                const float b0 = bias[gn], b1 = bias[gn + 1];
                const float s0 = ls[gn], s1 = ls[gn + 1];
                float2 v0 = *reinterpret_cast<float2*>(Cf + (long)gm0 * ldc + gn);
                float2 v1 = *reinterpret_cast<float2*>(Cf + (long)gm1 * ldc + gn);
                v0.x += (acc[i][j][0] + b0) * s0;
                v0.y += (acc[i][j][1] + b1) * s1;
                v1.x += (acc[i][j][2] + b0) * s0;
                v1.y += (acc[i][j][3] + b1) * s1;
                *reinterpret_cast<float2*>(Cf + (long)gm0 * ldc + gn) = v0;
                *reinterpret_cast<float2*>(Cf + (long)gm1 * ldc + gn) = v1;
            }
        }
    }
}

// ---------------- elementwise kernels ----------------
__global__ void convert_kernel(const float4* __restrict__ src,
                               __nv_bfloat16* __restrict__ dst, long n4) {
    long i = (long)blockIdx.x * blockDim.x + threadIdx.x;
    long stride = (long)gridDim.x * blockDim.x;
    __nv_bfloat162* d2 = reinterpret_cast<__nv_bfloat162*>(dst);
    for (; i < n4; i += stride) {
        float4 v = src[i];
        d2[2 * i]     = __floats2bfloat162_rn(v.x, v.y);
        d2[2 * i + 1] = __floats2bfloat162_rn(v.z, v.w);
    }
}

__global__ void copy_kernel(const float4* __restrict__ src, float4* __restrict__ dst) {
    long i = (long)blockIdx.x * blockDim.x + threadIdx.x;
    dst[i] = src[i];
}

__global__ __launch_bounds__(256) void ln_kernel(const float* __restrict__ x,
                                                 const float* __restrict__ w,
                                                 const float* __restrict__ b,
                                                 __nv_bfloat16* __restrict__ out) {
    int row = blockIdx.x;
    int t = threadIdx.x;
    const float4 v = reinterpret_cast<const float4*>(x + (long)row * DIM)[t];
    float s = v.x + v.y + v.z + v.w;
    float q = v.x * v.x + v.y * v.y + v.z * v.z + v.w * v.w;
    __shared__ float rs[8], rq[8];
    #pragma unroll
    for (int o = 16; o; o >>= 1) {
        s += __shfl_xor_sync(0xffffffffu, s, o);
        q += __shfl_xor_sync(0xffffffffu, q, o);
    }
    if ((t & 31) == 0) { rs[t >> 5] = s; rq[t >> 5] = q; }
    __syncthreads();
    float ts = 0.f, tq = 0.f;
    #pragma unroll
    for (int i = 0; i < 8; i++) { ts += rs[i]; tq += rq[i]; }
    float mu = ts * (1.f / DIM);
    float var = tq * (1.f / DIM) - mu * mu;
    float rstd = rsqrtf(var + 1e-5f);
    float4 wv = reinterpret_cast<const float4*>(w)[t];
    float4 bv = reinterpret_cast<const float4*>(b)[t];
    __nv_bfloat162* o2 = reinterpret_cast<__nv_bfloat162*>(out + (long)row * DIM);
    o2[2 * t]     = __floats2bfloat162_rn((v.x - mu) * rstd * wv.x + bv.x,
                                          (v.y - mu) * rstd * wv.y + bv.y);
    o2[2 * t + 1] = __floats2bfloat162_rn((v.z - mu) * rstd * wv.z + bv.z,
                                          (v.w - mu) * rstd * wv.w + bv.w);
}

__global__ __launch_bounds__(256) void softmax_kernel(const float* __restrict__ s,
                                                      __nv_bfloat16* __restrict__ p) {
    long row = blockIdx.x;
    int t = threadIdx.x;
    const float4 v = reinterpret_cast<const float4*>(s + row * 1024)[t];
    float m = fmaxf(fmaxf(v.x, v.y), fmaxf(v.z, v.w));
    __shared__ float red[8];
    #pragma unroll
    for (int o = 16; o; o >>= 1) m = fmaxf(m, __shfl_xor_sync(0xffffffffu, m, o));
    if ((t & 31) == 0) red[t >> 5] = m;
    __syncthreads();
    float bm = red[0];
    #pragma unroll
    for (int i = 1; i < 8; i++) bm = fmaxf(bm, red[i]);
    float e0 = __expf((v.x - bm) * ATTN_SCALE);
    float e1 = __expf((v.y - bm) * ATTN_SCALE);
    float e2 = __expf((v.z - bm) * ATTN_SCALE);
    float e3 = __expf((v.w - bm) * ATTN_SCALE);
    float su = e0 + e1 + e2 + e3;
    __syncthreads();
    #pragma unroll
    for (int o = 16; o; o >>= 1) su += __shfl_xor_sync(0xffffffffu, su, o);
    if ((t & 31) == 0) red[t >> 5] = su;
    __syncthreads();
    float tot = 0.f;
    #pragma unroll
    for (int i = 0; i < 8; i++) tot += red[i];
    float inv = 1.f / tot;
    __nv_bfloat162* p2 = reinterpret_cast<__nv_bfloat162*>(p + row * 1024);
    p2[2 * t]     = __floats2bfloat162_rn(e0 * inv, e1 * inv);
    p2[2 * t + 1] = __floats2bfloat162_rn(e2 * inv, e3 * inv);
}

__global__ void geglu_kernel(const __nv_bfloat16* __restrict__ u,
                             __nv_bfloat16* __restrict__ ff) {
    long n2 = (long)TOK * FF / 2;
    long i = (long)blockIdx.x * blockDim.x + threadIdx.x;
    long stride = (long)gridDim.x * blockDim.x;
    for (; i < n2; i += stride) {
        long row = i / (FF / 2);
        int j = (int)(i % (FF / 2));
        __nv_bfloat162 a2 = reinterpret_cast<const __nv_bfloat162*>(u + row * FF2X)[j];
        __nv_bfloat162 g2 = reinterpret_cast<const __nv_bfloat162*>(u + row * FF2X + FF)[j];
        float gx = __bfloat162float(g2.x);
        float gy = __bfloat162float(g2.y);
        float r0 = __bfloat162float(a2.x) * (0.5f * gx * (1.f + erff(gx * 0.70710678118654752f)));
        float r1 = __bfloat162float(a2.y) * (0.5f * gy * (1.f + erff(gy * 0.70710678118654752f)));
        reinterpret_cast<__nv_bfloat162*>(ff)[i] = __floats2bfloat162_rn(r0, r1);
    }
}

// ---------------- host ----------------
static void* symAddr(const void* sym) {
    void* p = nullptr;
    cudaGetSymbolAddress(&p, sym);
    return p;
}

extern "C" void kernel_launch(void* const* d_in, const int* in_sizes, int n_in,
                              void* d_out, int out_size) {
    const float* x    = (const float*)d_in[0];
    const float* ln1w = (const float*)d_in[1];
    const float* ln1b = (const float*)d_in[2];
    const float* wqkv = (const float*)d_in[3];
    const float* wout = (const float*)d_in[4];
    const float* bout = (const float*)d_in[5];
    const float* ls1  = (const float*)d_in[6];
    const float* ln2w = (const float*)d_in[7];
    const float* ln2b = (const float*)d_in[8];
    const float* wff1 = (const float*)d_in[9];
    const float* bff1 = (const float*)d_in[10];
    const float* wff2 = (const float*)d_in[11];
    const float* bff2 = (const float*)d_in[12];
    const float* ls2  = (const float*)d_in[13];
    float* out = (float*)d_out;

    __nv_bfloat16* WQ  = (__nv_bfloat16*)symAddr(g_wqkv);
    __nv_bfloat16* WO  = (__nv_bfloat16*)symAddr(g_wout);
    __nv_bfloat16* W1  = (__nv_bfloat16*)symAddr(g_wff1);
    __nv_bfloat16* W2  = (__nv_bfloat16*)symAddr(g_wff2);
    __nv_bfloat16* H   = (__nv_bfloat16*)symAddr(g_h);
    __nv_bfloat16* QKV = (__nv_bfloat16*)symAddr(g_qkv);
    float*         SC  = (float*)symAddr(g_sc);
    __nv_bfloat16* PR  = (__nv_bfloat16*)symAddr(g_pr);
    __nv_bfloat16* O   = (__nv_bfloat16*)symAddr(g_o);
    __nv_bfloat16* U   = (__nv_bfloat16*)symAddr(g_u);
    __nv_bfloat16* FFB = (__nv_bfloat16*)symAddr(g_ff);

    // smem sizes: stage = A(128*72*2) + B bytes, x3 stages
    constexpr int SM_KN128 = (128 * 72 * 2 + 64 * 136 * 2) * 3;   // 107520
    constexpr int SM_NK128 = (128 * 72 * 2 + 128 * 72 * 2) * 3;   // 110592
    constexpr int SM_KN64  = (128 * 72 * 2 + 64 * 72 * 2) * 3;    // 82944
    cudaFuncSetAttribute(mma_gemm<128, 128, 1, 0>, cudaFuncAttributeMaxDynamicSharedMemorySize, SM_KN128);
    cudaFuncSetAttribute(mma_gemm<128, 128, 1, 2>, cudaFuncAttributeMaxDynamicSharedMemorySize, SM_KN128);
    cudaFuncSetAttribute(mma_gemm<128, 128, 0, 1>, cudaFuncAttributeMaxDynamicSharedMemorySize, SM_NK128);
    cudaFuncSetAttribute(mma_gemm<128, 64, 1, 0>,  cudaFuncAttributeMaxDynamicSharedMemorySize, SM_KN64);

    // bf16 weights (native [K,N] layout, no transpose)
    convert_kernel<<<2048, 256>>>((const float4*)wqkv, WQ, (long)DEPTH * DIM * QKV3 / 4);
    convert_kernel<<<2048, 256>>>((const float4*)wout, WO, (long)DEPTH * DIM * DIM / 4);
    convert_kernel<<<2048, 256>>>((const float4*)wff1, W1, (long)DEPTH * DIM * FF2X / 4);
    convert_kernel<<<2048, 256>>>((const float4*)wff2, W2, (long)DEPTH * FF * DIM / 4);

    copy_kernel<<<2048, 256>>>((const float4*)x, (float4*)out);

    for (int l = 0; l < DEPTH; l++) {
        const __nv_bfloat16* Wq = WQ + (long)l * DIM * QKV3;
        const __nv_bfloat16* Wo = WO + (long)l * DIM * DIM;
        const __nv_bfloat16* Wf1 = W1 + (long)l * DIM * FF2X;
        const __nv_bfloat16* Wf2 = W2 + (long)l * FF * DIM;

        ln_kernel<<<TOK, 256>>>(out, ln1w + l * DIM, ln1b + l * DIM, H);

        // QKV = H @ Wq  [2048 x 3072], K=1024, B=[K,N]
        mma_gemm<128, 128, 1, 0><<<dim3(24, 16, 1), 256, SM_KN128>>>(
            H, Wq, QKV, nullptr, nullptr, DIM, QKV3, QKV3, DIM, 0, 0, 0, 0, 0, 0);

        // scores = Q @ K^T per (b,h)  [1024 x 1024], K=64, B=[N,K] (K rows of QKV)
        mma_gemm<128, 128, 0, 1><<<dim3(8, 8, 32), 256, SM_NK128>>>(
            QKV, QKV + DIM, SC, nullptr, nullptr, QKV3, QKV3, SEQ, DHEAD,
            (long)SEQ * QKV3, 64L, (long)SEQ * QKV3, 64L,
            (long)HEADS * SEQ * SEQ, (long)SEQ * SEQ);

        softmax_kernel<<<BATCH * HEADS * SEQ, 256>>>(SC, PR);

        // O = P @ V per (b,h)  [1024 x 64], K=1024, B = V rows of QKV = [K,N]
        mma_gemm<128, 64, 1, 0><<<dim3(1, 8, 32), 256, SM_KN64>>>(
            PR, QKV + 2048, O, nullptr, nullptr, SEQ, QKV3, DIM, SEQ,
            (long)HEADS * SEQ * SEQ, (long)SEQ * SEQ,
            (long)SEQ * QKV3, 64L,
            (long)SEQ * DIM, 64L);

        // out += (O @ Wo + bout) * ls1  [2048 x 1024], K=1024
        mma_gemm<128, 128, 1, 2><<<dim3(8, 16, 1), 256, SM_KN128>>>(
            O, Wo, out, bout + l * DIM, ls1 + l * DIM, DIM, DIM, DIM, DIM, 0, 0, 0, 0, 0, 0);

        ln_kernel<<<TOK, 256>>>(out, ln2w + l * DIM, ln2b + l * DIM, H);

        // U = H @ Wf1 + bff1  [2048 x 8192], K=1024
        mma_gemm<128, 128, 1, 0><<<dim3(64, 16, 1), 256, SM_KN128>>>(
            H, Wf1, U, bff1 + l * FF2X, nullptr, DIM, FF2X, FF2X, DIM, 0, 0, 0, 0, 0, 0);

        geglu_kernel<<<4096, 256>>>(U, FFB);

        // out += (FF @ Wf2 + bff2) * ls2  [2048 x 1024], K=4096
        mma_gemm<128, 128, 1, 2><<<dim3(8, 16, 1), 256, SM_KN128>>>(
            FFB, Wf2, out, bff2 + l * DIM, ls2 + l * DIM, FF, DIM, DIM, FF, 0, 0, 0, 0, 0, 0);
    }
}

// round 5
// speedup vs baseline: 2.5573x; 1.2019x over previous
#include <cuda_runtime.h>
#include <cuda_bf16.h>
#include <cstdint>

// ---------------- problem constants ----------------
#define SEQ    1024
#define BATCH  2
#define TOK    2048
#define DIM    1024
#define HEADS  16
#define DHEAD  64
#define QKV3   3072
#define FF     4096
#define FF2X   8192
#define DEPTH  4

// ---------------- device scratch ----------------
__device__ __align__(128) __nv_bfloat16 g_wqkv[(long)DEPTH * DIM * QKV3];
__device__ __align__(128) __nv_bfloat16 g_wout[(long)DEPTH * DIM * DIM];
__device__ __align__(128) __nv_bfloat16 g_wff1[(long)DEPTH * DIM * FF2X];
__device__ __align__(128) __nv_bfloat16 g_wff2[(long)DEPTH * FF * DIM];
__device__ __align__(128) __nv_bfloat16 g_h   [(long)TOK * DIM];
__device__ __align__(128) __nv_bfloat16 g_qkv [(long)TOK * QKV3];
__device__ __align__(128) __nv_bfloat16 g_o   [(long)TOK * DIM];
__device__ __align__(128) __nv_bfloat16 g_u   [(long)TOK * FF2X];
__device__ __align__(128) __nv_bfloat16 g_ff  [(long)TOK * FF];

// ---------------- helpers ----------------
__device__ __forceinline__ uint32_t smem_u32(const void* p) {
    uint32_t a;
    asm("{ .reg .u64 t; cvta.to.shared.u64 t, %1; cvt.u32.u64 %0, t; }" : "=r"(a) : "l"(p));
    return a;
}
__device__ __forceinline__ void cpasync16(uint32_t dst, const void* src) {
    asm volatile("cp.async.cg.shared.global [%0], [%1], 16;" :: "r"(dst), "l"(src));
}
__device__ __forceinline__ void ldsm_x4(uint32_t* r, uint32_t addr) {
    asm volatile("ldmatrix.sync.aligned.m8n8.x4.shared.b16 {%0,%1,%2,%3}, [%4];"
                 : "=r"(r[0]), "=r"(r[1]), "=r"(r[2]), "=r"(r[3]) : "r"(addr));
}
__device__ __forceinline__ void ldsm_x2t(uint32_t* r, uint32_t addr) {
    asm volatile("ldmatrix.sync.aligned.m8n8.x2.trans.shared.b16 {%0,%1}, [%2];"
                 : "=r"(r[0]), "=r"(r[1]) : "r"(addr));
}
__device__ __forceinline__ void ldsm_x2(uint32_t* r, uint32_t addr) {
    asm volatile("ldmatrix.sync.aligned.m8n8.x2.shared.b16 {%0,%1}, [%2];"
                 : "=r"(r[0]), "=r"(r[1]) : "r"(addr));
}
__device__ __forceinline__ void mma16816(float* c, const uint32_t* a, const uint32_t* b) {
    asm volatile(
        "mma.sync.aligned.m16n8k16.row.col.f32.bf16.bf16.f32 "
        "{%0,%1,%2,%3}, {%4,%5,%6,%7}, {%8,%9}, {%0,%1,%2,%3};"
        : "+f"(c[0]), "+f"(c[1]), "+f"(c[2]), "+f"(c[3])
        : "r"(a[0]), "r"(a[1]), "r"(a[2]), "r"(a[3]), "r"(b[0]), "r"(b[1]));
}

// ---------------- pipelined mma.sync GEMM (weights path) ----------------
// C[M,N] = A[M,K] @ B[K,N].  A bf16 K-major, B row-major [K,N].
// EPI: 0 = bf16 store (+opt bias), 2 = fp32 residual += (acc+bias)*ls
template <int ROWS, int CPR, int STRIDE>
__device__ __forceinline__ void stage_t(uint32_t dst, const __nv_bfloat16* g, int ld) {
    #pragma unroll
    for (int it = 0; it < ROWS * CPR / 256; it++) {
        int s = threadIdx.x + it * 256;
        int r = s / CPR, j = s % CPR;
        cpasync16(dst + (r * STRIDE + j * 8) * 2, g + (long)r * ld + j * 8);
    }
}

template <int BM, int BN, int EPI>
__global__ void __launch_bounds__(256, 2) mma_gemm(
    const __nv_bfloat16* __restrict__ A, const __nv_bfloat16* __restrict__ B,
    void* __restrict__ Cv, const float* __restrict__ bias, const float* __restrict__ ls,
    int lda, int ldb, int ldc, int K) {
    constexpr int BK = 64;
    constexpr int AST = BK + 8;
    constexpr int BST = BN + 8;
    constexpr int ABYTES = BM * AST * 2;
    constexpr int BBYTES = BK * BST * 2;
    constexpr int STAGE = ABYTES + BBYTES;

    extern __shared__ __align__(128) char smem[];
    const uint32_t sb = smem_u32(smem);

    const int tid = threadIdx.x;
    const int wid = tid >> 5, l = tid & 31;

    constexpr int WROWS = 2, WCOLS = 4;
    constexpr int WTM = BM / WROWS;
    constexpr int WTN = BN / WCOLS;
    constexpr int FM = WTM / 16;
    constexpr int FN = WTN / 8;
    const int wm = (wid / WCOLS) * WTM;
    const int wn = (wid % WCOLS) * WTN;

    const int m0 = blockIdx.y * BM, n0 = blockIdx.x * BN;
    A += (long)m0 * lda;
    B += n0;

    const int nch = K >> 6;
    stage_t<BM, 8, AST>(sb, A, lda);
    stage_t<BK, BN / 8, BST>(sb + ABYTES, B, ldb);
    asm volatile("cp.async.commit_group;" ::: "memory");
    stage_t<BM, 8, AST>(sb + STAGE, A + 64, lda);
    stage_t<BK, BN / 8, BST>(sb + STAGE + ABYTES, B + 64L * ldb, ldb);
    asm volatile("cp.async.commit_group;" ::: "memory");

    float acc[FM][FN][4];
    #pragma unroll
    for (int i = 0; i < FM; i++)
        #pragma unroll
        for (int j = 0; j < FN; j++)
            #pragma unroll
            for (int q = 0; q < 4; q++) acc[i][j][q] = 0.f;

    for (int c = 0; c < nch; c++) {
        if (c + 1 < nch) asm volatile("cp.async.wait_group 1;" ::: "memory");
        else             asm volatile("cp.async.wait_group 0;" ::: "memory");
        __syncthreads();

        const uint32_t sA = sb + (c % 3) * STAGE;
        const uint32_t sB = sA + ABYTES;

        #pragma unroll
        for (int kk = 0; kk < 4; kk++) {
            uint32_t af[FM][4], bf[FN][2];
            #pragma unroll
            for (int i = 0; i < FM; i++)
                ldsm_x4(af[i], sA + ((wm + i * 16 + (l & 15)) * AST + kk * 16 + (l >> 4) * 8) * 2);
            #pragma unroll
            for (int j = 0; j < FN; j++)
                ldsm_x2t(bf[j], sB + ((kk * 16 + (l & 15)) * BST + wn + j * 8) * 2);
            #pragma unroll
            for (int i = 0; i < FM; i++)
                #pragma unroll
                for (int j = 0; j < FN; j++)
                    mma16816(acc[i][j], af[i], bf[j]);
        }

        if (c + 2 < nch) {
            const uint32_t dA = sb + ((c + 2) % 3) * STAGE;
            stage_t<BM, 8, AST>(dA, A + (long)(c + 2) * 64, lda);
            stage_t<BK, BN / 8, BST>(dA + ABYTES, B + (long)(c + 2) * 64 * ldb, ldb);
            asm volatile("cp.async.commit_group;" ::: "memory");
        }
    }

    const int tr = l >> 2;
    const int tc = (l & 3) * 2;
    #pragma unroll
    for (int i = 0; i < FM; i++) {
        #pragma unroll
        for (int j = 0; j < FN; j++) {
            const int gm0 = m0 + wm + i * 16 + tr;
            const int gm1 = gm0 + 8;
            const int gn = n0 + wn + j * 8 + tc;
            if (EPI == 0) {
                __nv_bfloat16* Cb = (__nv_bfloat16*)Cv;
                float b0 = 0.f, b1 = 0.f;
                if (bias) { b0 = bias[gn]; b1 = bias[gn + 1]; }
                *reinterpret_cast<__nv_bfloat162*>(Cb + (long)gm0 * ldc + gn) =
                    __floats2bfloat162_rn(acc[i][j][0] + b0, acc[i][j][1] + b1);
                *reinterpret_cast<__nv_bfloat162*>(Cb + (long)gm1 * ldc + gn) =
                    __floats2bfloat162_rn(acc[i][j][2] + b0, acc[i][j][3] + b1);
            } else {
                float* Cf = (float*)Cv;
                const float b0 = bias[gn], b1 = bias[gn + 1];
                const float s0 = ls[gn], s1 = ls[gn + 1];
                float2 v0 = *reinterpret_cast<float2*>(Cf + (long)gm0 * ldc + gn);
                float2 v1 = *reinterpret_cast<float2*>(Cf + (long)gm1 * ldc + gn);
                v0.x += (acc[i][j][0] + b0) * s0;
                v0.y += (acc[i][j][1] + b1) * s1;
                v1.x += (acc[i][j][2] + b0) * s0;
                v1.y += (acc[i][j][3] + b1) * s1;
                *reinterpret_cast<float2*>(Cf + (long)gm0 * ldc + gn) = v0;
                *reinterpret_cast<float2*>(Cf + (long)gm1 * ldc + gn) = v1;
            }
        }
    }
}

// ---------------- fused flash attention ----------------
// One block per (q-tile 128 rows, bh). Online softmax, K/V tiles of 64 rows,
// triple-buffered cp.async. Scale folded into exp2 domain.
__global__ void __launch_bounds__(256) flash_kernel(
    const __nv_bfloat16* __restrict__ qkv, __nv_bfloat16* __restrict__ o) {
    constexpr int QST = 72, KST = 72;
    constexpr int QBYTES = 128 * QST * 2;
    constexpr int KVB = 2 * 64 * KST * 2;  // one K + one V tile
    extern __shared__ __align__(128) char smem[];
    const uint32_t sb = smem_u32(smem);
    const int tid = threadIdx.x, wid = tid >> 5, l = tid & 31;
    const int qt = blockIdx.x, bh = blockIdx.y;
    const int b = bh >> 4, h = bh & 15;
    const __nv_bfloat16* Qg = qkv + (long)b * SEQ * QKV3 + (long)(qt * 128) * QKV3 + h * 64;
    const __nv_bfloat16* Kg = qkv + (long)b * SEQ * QKV3 + 1024 + h * 64;
    const __nv_bfloat16* Vg = qkv + (long)b * SEQ * QKV3 + 2048 + h * 64;

    // stage Q (128x64)
    #pragma unroll
    for (int it = 0; it < 4; it++) {
        int s = tid + it * 256, r = s >> 3, j = s & 7;
        cpasync16(sb + (r * QST + j * 8) * 2, Qg + (long)r * QKV3 + j * 8);
    }
    auto stage_kv = [&](int slot, int c) {
        uint32_t base = sb + QBYTES + slot * KVB;
        const __nv_bfloat16* kg = Kg + (long)(c * 64) * QKV3;
        const __nv_bfloat16* vg = Vg + (long)(c * 64) * QKV3;
        #pragma unroll
        for (int it = 0; it < 2; it++) {
            int s = tid + it * 256, r = s >> 3, j = s & 7;
            cpasync16(base + (r * KST + j * 8) * 2, kg + (long)r * QKV3 + j * 8);
            cpasync16(base + 64 * KST * 2 + (r * KST + j * 8) * 2, vg + (long)r * QKV3 + j * 8);
        }
    };
    stage_kv(0, 0);
    asm volatile("cp.async.commit_group;" ::: "memory");
    stage_kv(1, 1);
    asm volatile("cp.async.commit_group;" ::: "memory");

    float oacc[8][4];
    #pragma unroll
    for (int j = 0; j < 8; j++)
        #pragma unroll
        for (int q = 0; q < 4; q++) oacc[j][q] = 0.f;
    float m0 = -1e30f, m1 = -1e30f, sum0 = 0.f, sum1 = 0.f;
    const int wm = wid * 16;
    constexpr float CS = 0.125f * 1.4426950408889634f;  // scale * log2(e)

    for (int c = 0; c < 16; c++) {
        if (c < 15) asm volatile("cp.async.wait_group 1;" ::: "memory");
        else        asm volatile("cp.async.wait_group 0;" ::: "memory");
        __syncthreads();
        const uint32_t sK = sb + QBYTES + (c % 3) * KVB;
        const uint32_t sV = sK + 64 * KST * 2;

        // S = Q @ K^T  (16x64 per warp)
        float sacc[8][4];
        #pragma unroll
        for (int j = 0; j < 8; j++)
            #pragma unroll
            for (int q = 0; q < 4; q++) sacc[j][q] = 0.f;
        #pragma unroll
        for (int kk = 0; kk < 4; kk++) {
            uint32_t af[4];
            ldsm_x4(af, sb + ((wm + (l & 15)) * QST + kk * 16 + (l >> 4) * 8) * 2);
            #pragma unroll
            for (int j = 0; j < 8; j++) {
                uint32_t bf[2];
                ldsm_x2(bf, sK + ((j * 8 + (l & 7)) * KST + kk * 16 + (l >> 3) * 8) * 2);
                mma16816(sacc[j], af, bf);
            }
        }
        // online softmax (exp2 domain)
        float mx0 = -1e30f, mx1 = -1e30f;
        #pragma unroll
        for (int j = 0; j < 8; j++) {
            sacc[j][0] *= CS; sacc[j][1] *= CS; sacc[j][2] *= CS; sacc[j][3] *= CS;
            mx0 = fmaxf(mx0, fmaxf(sacc[j][0], sacc[j][1]));
            mx1 = fmaxf(mx1, fmaxf(sacc[j][2], sacc[j][3]));
        }
        mx0 = fmaxf(mx0, __shfl_xor_sync(~0u, mx0, 1));
        mx0 = fmaxf(mx0, __shfl_xor_sync(~0u, mx0, 2));
        mx1 = fmaxf(mx1, __shfl_xor_sync(~0u, mx1, 1));
        mx1 = fmaxf(mx1, __shfl_xor_sync(~0u, mx1, 2));
        const float mn0 = fmaxf(m0, mx0), mn1 = fmaxf(m1, mx1);
        const float al0 = exp2f(m0 - mn0), al1 = exp2f(m1 - mn1);
        m0 = mn0; m1 = mn1;
        sum0 *= al0; sum1 *= al1;
        uint32_t pb[8][2];
        #pragma unroll
        for (int j = 0; j < 8; j++) {
            float p0 = exp2f(sacc[j][0] - mn0), p1 = exp2f(sacc[j][1] - mn0);
            float p2 = exp2f(sacc[j][2] - mn1), p3 = exp2f(sacc[j][3] - mn1);
            sum0 += p0 + p1; sum1 += p2 + p3;
            __nv_bfloat162 t0 = __floats2bfloat162_rn(p0, p1);
            __nv_bfloat162 t1 = __floats2bfloat162_rn(p2, p3);
            pb[j][0] = *reinterpret_cast<uint32_t*>(&t0);
            pb[j][1] = *reinterpret_cast<uint32_t*>(&t1);
            oacc[j][0] *= al0; oacc[j][1] *= al0;
            oacc[j][2] *= al1; oacc[j][3] *= al1;
        }
        // O += P @ V  (accumulator frags re-used as A operands)
        #pragma unroll
        for (int kk2 = 0; kk2 < 4; kk2++) {
            uint32_t af2[4] = { pb[2 * kk2][0], pb[2 * kk2][1],
                                pb[2 * kk2 + 1][0], pb[2 * kk2 + 1][1] };
            #pragma unroll
            for (int nj = 0; nj < 8; nj++) {
                uint32_t bv[2];
                ldsm_x2t(bv, sV + ((kk2 * 16 + (l & 15)) * KST + nj * 8) * 2);
                mma16816(oacc[nj], af2, bv);
            }
        }
        if (c + 2 < 16) {
            stage_kv((c + 2) % 3, c + 2);
            asm volatile("cp.async.commit_group;" ::: "memory");
        }
    }
    sum0 += __shfl_xor_sync(~0u, sum0, 1); sum0 += __shfl_xor_sync(~0u, sum0, 2);
    sum1 += __shfl_xor_sync(~0u, sum1, 1); sum1 += __shfl_xor_sync(~0u, sum1, 2);
    const float inv0 = 1.f / sum0, inv1 = 1.f / sum1;
    const int tr = l >> 2, tc = (l & 3) * 2;
    __nv_bfloat16* Ob = o + (long)(b * SEQ + qt * 128 + wm) * DIM + h * 64;
    #pragma unroll
    for (int nj = 0; nj < 8; nj++) {
        *reinterpret_cast<__nv_bfloat162*>(Ob + (long)tr * DIM + nj * 8 + tc) =
            __floats2bfloat162_rn(oacc[nj][0] * inv0, oacc[nj][1] * inv0);
        *reinterpret_cast<__nv_bfloat162*>(Ob + (long)(tr + 8) * DIM + nj * 8 + tc) =
            __floats2bfloat162_rn(oacc[nj][2] * inv1, oacc[nj][3] * inv1);
    }
}

// ---------------- elementwise kernels ----------------
__global__ void convert_kernel(const float4* __restrict__ src,
                               __nv_bfloat16* __restrict__ dst, long n4) {
    long i = (long)blockIdx.x * blockDim.x + threadIdx.x;
    long stride = (long)gridDim.x * blockDim.x;
    __nv_bfloat162* d2 = reinterpret_cast<__nv_bfloat162*>(dst);
    for (; i < n4; i += stride) {
        float4 v = src[i];
        d2[2 * i]     = __floats2bfloat162_rn(v.x, v.y);
        d2[2 * i + 1] = __floats2bfloat162_rn(v.z, v.w);
    }
}

__global__ void copy_kernel(const float4* __restrict__ src, float4* __restrict__ dst) {
    long i = (long)blockIdx.x * blockDim.x + threadIdx.x;
    dst[i] = src[i];
}

__global__ __launch_bounds__(256) void ln_kernel(const float* __restrict__ x,
                                                 const float* __restrict__ w,
                                                 const float* __restrict__ b,
                                                 __nv_bfloat16* __restrict__ out) {
    int row = blockIdx.x;
    int t = threadIdx.x;
    const float4 v = reinterpret_cast<const float4*>(x + (long)row * DIM)[t];
    float s = v.x + v.y + v.z + v.w;
    float q = v.x * v.x + v.y * v.y + v.z * v.z + v.w * v.w;
    __shared__ float rs[8], rq[8];
    #pragma unroll
    for (int o = 16; o; o >>= 1) {
        s += __shfl_xor_sync(0xffffffffu, s, o);
        q += __shfl_xor_sync(0xffffffffu, q, o);
    }
    if ((t & 31) == 0) { rs[t >> 5] = s; rq[t >> 5] = q; }
    __syncthreads();
    float ts = 0.f, tq = 0.f;
    #pragma unroll
    for (int i = 0; i < 8; i++) { ts += rs[i]; tq += rq[i]; }
    float mu = ts * (1.f / DIM);
    float var = tq * (1.f / DIM) - mu * mu;
    float rstd = rsqrtf(var + 1e-5f);
    float4 wv = reinterpret_cast<const float4*>(w)[t];
    float4 bv = reinterpret_cast<const float4*>(b)[t];
    __nv_bfloat162* o2 = reinterpret_cast<__nv_bfloat162*>(out + (long)row * DIM);
    o2[2 * t]     = __floats2bfloat162_rn((v.x - mu) * rstd * wv.x + bv.x,
                                          (v.y - mu) * rstd * wv.y + bv.y);
    o2[2 * t + 1] = __floats2bfloat162_rn((v.z - mu) * rstd * wv.z + bv.z,
                                          (v.w - mu) * rstd * wv.w + bv.w);
}

__global__ void geglu_kernel(const __nv_bfloat16* __restrict__ u,
                             __nv_bfloat16* __restrict__ ff) {
    long n2 = (long)TOK * FF / 2;
    long i = (long)blockIdx.x * blockDim.x + threadIdx.x;
    long stride = (long)gridDim.x * blockDim.x;
    for (; i < n2; i += stride) {
        long row = i / (FF / 2);
        int j = (int)(i % (FF / 2));
        __nv_bfloat162 a2 = reinterpret_cast<const __nv_bfloat162*>(u + row * FF2X)[j];
        __nv_bfloat162 g2 = reinterpret_cast<const __nv_bfloat162*>(u + row * FF2X + FF)[j];
        float gx = __bfloat162float(g2.x);
        float gy = __bfloat162float(g2.y);
        float r0 = __bfloat162float(a2.x) * (0.5f * gx * (1.f + erff(gx * 0.70710678118654752f)));
        float r1 = __bfloat162float(a2.y) * (0.5f * gy * (1.f + erff(gy * 0.70710678118654752f)));
        reinterpret_cast<__nv_bfloat162*>(ff)[i] = __floats2bfloat162_rn(r0, r1);
    }
}

// ---------------- host ----------------
static void* symAddr(const void* sym) {
    void* p = nullptr;
    cudaGetSymbolAddress(&p, sym);
    return p;
}

extern "C" void kernel_launch(void* const* d_in, const int* in_sizes, int n_in,
                              void* d_out, int out_size) {
    const float* x    = (const float*)d_in[0];
    const float* ln1w = (const float*)d_in[1];
    const float* ln1b = (const float*)d_in[2];
    const float* wqkv = (const float*)d_in[3];
    const float* wout = (const float*)d_in[4];
    const float* bout = (const float*)d_in[5];
    const float* ls1  = (const float*)d_in[6];
    const float* ln2w = (const float*)d_in[7];
    const float* ln2b = (const float*)d_in[8];
    const float* wff1 = (const float*)d_in[9];
    const float* bff1 = (const float*)d_in[10];
    const float* wff2 = (const float*)d_in[11];
    const float* bff2 = (const float*)d_in[12];
    const float* ls2  = (const float*)d_in[13];
    float* out = (float*)d_out;

    __nv_bfloat16* WQ  = (__nv_bfloat16*)symAddr(g_wqkv);
    __nv_bfloat16* WO  = (__nv_bfloat16*)symAddr(g_wout);
    __nv_bfloat16* W1  = (__nv_bfloat16*)symAddr(g_wff1);
    __nv_bfloat16* W2  = (__nv_bfloat16*)symAddr(g_wff2);
    __nv_bfloat16* H   = (__nv_bfloat16*)symAddr(g_h);
    __nv_bfloat16* QKV = (__nv_bfloat16*)symAddr(g_qkv);
    __nv_bfloat16* O   = (__nv_bfloat16*)symAddr(g_o);
    __nv_bfloat16* U   = (__nv_bfloat16*)symAddr(g_u);
    __nv_bfloat16* FFB = (__nv_bfloat16*)symAddr(g_ff);

    constexpr int SM_GEMM = (128 * 72 * 2 + 64 * 136 * 2) * 3;     // 107520
    constexpr int SM_FL   = 128 * 72 * 2 + 3 * (2 * 64 * 72 * 2);  // 73728
    cudaFuncSetAttribute(mma_gemm<128, 128, 0>, cudaFuncAttributeMaxDynamicSharedMemorySize, SM_GEMM);
    cudaFuncSetAttribute(mma_gemm<128, 128, 2>, cudaFuncAttributeMaxDynamicSharedMemorySize, SM_GEMM);
    cudaFuncSetAttribute(flash_kernel, cudaFuncAttributeMaxDynamicSharedMemorySize, SM_FL);

    convert_kernel<<<2048, 256>>>((const float4*)wqkv, WQ, (long)DEPTH * DIM * QKV3 / 4);
    convert_kernel<<<2048, 256>>>((const float4*)wout, WO, (long)DEPTH * DIM * DIM / 4);
    convert_kernel<<<2048, 256>>>((const float4*)wff1, W1, (long)DEPTH * DIM * FF2X / 4);
    convert_kernel<<<2048, 256>>>((const float4*)wff2, W2, (long)DEPTH * FF * DIM / 4);

    copy_kernel<<<2048, 256>>>((const float4*)x, (float4*)out);

    for (int l = 0; l < DEPTH; l++) {
        const __nv_bfloat16* Wq = WQ + (long)l * DIM * QKV3;
        const __nv_bfloat16* Wo = WO + (long)l * DIM * DIM;
        const __nv_bfloat16* Wf1 = W1 + (long)l * DIM * FF2X;
        const __nv_bfloat16* Wf2 = W2 + (long)l * FF * DIM;

        ln_kernel<<<TOK, 256>>>(out, ln1w + l * DIM, ln1b + l * DIM, H);

        // QKV = H @ Wq  [2048 x 3072], K=1024
        mma_gemm<128, 128, 0><<<dim3(24, 16), 256, SM_GEMM>>>(
            H, Wq, QKV, nullptr, nullptr, DIM, QKV3, QKV3, DIM);

        // fused attention -> O [2048 x 1024] bf16
        flash_kernel<<<dim3(8, 32), 256, SM_FL>>>(QKV, O);

        // out += (O @ Wo + bout) * ls1  [2048 x 1024], K=1024
        mma_gemm<128, 128, 2><<<dim3(8, 16), 256, SM_GEMM>>>(
            O, Wo, out, bout + l * DIM, ls1 + l * DIM, DIM, DIM, DIM, DIM);

        ln_kernel<<<TOK, 256>>>(out, ln2w + l * DIM, ln2b + l * DIM, H);

        // U = H @ Wf1 + bff1  [2048 x 8192], K=1024
        mma_gemm<128, 128, 0><<<dim3(64, 16), 256, SM_GEMM>>>(
            H, Wf1, U, bff1 + l * FF2X, nullptr, DIM, FF2X, FF2X, DIM);

        geglu_kernel<<<4096, 256>>>(U, FFB);

        // out += (FF @ Wf2 + bff2) * ls2  [2048 x 1024], K=4096
        mma_gemm<128, 128, 2><<<dim3(8, 16), 256, SM_GEMM>>>(
            FFB, Wf2, out, bff2 + l * DIM, ls2 + l * DIM, FF, DIM, DIM, FF);
    }
}

// round 6
// speedup vs baseline: 2.6910x; 1.0523x over previous
#include <cuda_runtime.h>
#include <cuda_bf16.h>
#include <cstdint>

// ---------------- problem constants ----------------
#define SEQ    1024
#define BATCH  2
#define TOK    2048
#define DIM    1024
#define HEADS  16
#define DHEAD  64
#define QKV3   3072
#define FF     4096
#define FF2X   8192
#define DEPTH  4

// ---------------- device scratch ----------------
__device__ __align__(128) __nv_bfloat16 g_wqkv[(long)DEPTH * DIM * QKV3];
__device__ __align__(128) __nv_bfloat16 g_wout[(long)DEPTH * DIM * DIM];
__device__ __align__(128) __nv_bfloat16 g_wff1[(long)DEPTH * DIM * FF2X];
__device__ __align__(128) __nv_bfloat16 g_wff2[(long)DEPTH * FF * DIM];
__device__ __align__(128) __nv_bfloat16 g_h   [(long)TOK * DIM];
__device__ __align__(128) __nv_bfloat16 g_qkv [(long)TOK * QKV3];
__device__ __align__(128) __nv_bfloat16 g_o   [(long)TOK * DIM];
__device__ __align__(128) __nv_bfloat16 g_ff  [(long)TOK * FF];

// ---------------- helpers ----------------
__device__ __forceinline__ uint32_t smem_u32(const void* p) {
    uint32_t a;
    asm("{ .reg .u64 t; cvta.to.shared.u64 t, %1; cvt.u32.u64 %0, t; }" : "=r"(a) : "l"(p));
    return a;
}
__device__ __forceinline__ void cpasync16(uint32_t dst, const void* src) {
    asm volatile("cp.async.cg.shared.global [%0], [%1], 16;" :: "r"(dst), "l"(src));
}
__device__ __forceinline__ void ldsm_x4(uint32_t* r, uint32_t addr) {
    asm volatile("ldmatrix.sync.aligned.m8n8.x4.shared.b16 {%0,%1,%2,%3}, [%4];"
                 : "=r"(r[0]), "=r"(r[1]), "=r"(r[2]), "=r"(r[3]) : "r"(addr));
}
__device__ __forceinline__ void ldsm_x4t(uint32_t* r, uint32_t addr) {
    asm volatile("ldmatrix.sync.aligned.m8n8.x4.trans.shared.b16 {%0,%1,%2,%3}, [%4];"
                 : "=r"(r[0]), "=r"(r[1]), "=r"(r[2]), "=r"(r[3]) : "r"(addr));
}
__device__ __forceinline__ void mma16816(float* c, const uint32_t* a, const uint32_t* b) {
    asm volatile(
        "mma.sync.aligned.m16n8k16.row.col.f32.bf16.bf16.f32 "
        "{%0,%1,%2,%3}, {%4,%5,%6,%7}, {%8,%9}, {%0,%1,%2,%3};"
        : "+f"(c[0]), "+f"(c[1]), "+f"(c[2]), "+f"(c[3])
        : "r"(a[0]), "r"(a[1]), "r"(a[2]), "r"(a[3]), "r"(b[0]), "r"(b[1]));
}
__device__ __forceinline__ float gelu_exact(float x) {
    return 0.5f * x * (1.f + erff(x * 0.70710678118654752f));
}

// ---------------- pipelined mma.sync GEMM ----------------
// C[M,N] = A[M,K] @ B[K,N].  A bf16 K-major, B row-major [K,N].
// EPI: 0 = bf16 store (+opt bias), 2 = fp32 residual += (acc+bias)*ls,
//      3 = fused GEGLU: block covers out cols [n0, n0+64); B tile = cols
//          [n0,n0+64) | [4096+n0, 4096+n0+64); epilogue writes
//          (a+ba)*gelu(g+bg) to bf16 C (ldc cols).
template <int ROWS, int CPR, int STRIDE>
__device__ __forceinline__ void stage_t(uint32_t dst, const __nv_bfloat16* g, int ld) {
    #pragma unroll
    for (int it = 0; it < ROWS * CPR / 256; it++) {
        int s = threadIdx.x + it * 256;
        int r = s / CPR, j = s % CPR;
        cpasync16(dst + (r * STRIDE + j * 8) * 2, g + (long)r * ld + j * 8);
    }
}

template <int BM, int BN, int EPI>
__global__ void __launch_bounds__(256, 2) mma_gemm(
    const __nv_bfloat16* __restrict__ A, const __nv_bfloat16* __restrict__ B,
    void* __restrict__ Cv, const float* __restrict__ bias, const float* __restrict__ ls,
    int lda, int ldb, int ldc, int K) {
    constexpr int BK = 64;
    constexpr int AST = BK + 8;
    constexpr int BST = BN + 8;
    constexpr int ABYTES = BM * AST * 2;
    constexpr int BBYTES = BK * BST * 2;
    constexpr int STAGE = ABYTES + BBYTES;

    extern __shared__ __align__(128) char smem[];
    const uint32_t sb = smem_u32(smem);

    const int tid = threadIdx.x;
    const int wid = tid >> 5, l = tid & 31;

    constexpr int WTM = BM / 2;
    constexpr int FM = WTM / 16;
    constexpr int FN = 4;   // 32 cols per warp
    const int wm = (wid >> 2) * WTM;
    const int wn = (EPI == 3) ? ((wid & 3) * 16) : ((wid & 3) * 32);

    const int m0 = blockIdx.y * BM;
    const int n0 = blockIdx.x * ((EPI == 3) ? 64 : BN);
    A += (long)m0 * lda;
    B += n0;

    // B staging (one chunk of 64 k-rows)
    auto stage_B = [&](uint32_t dst, int c) {
        if (EPI == 3) {
            const __nv_bfloat16* Bc = B + (long)c * 64 * ldb;
            #pragma unroll
            for (int it = 0; it < 4; it++) {
                int s = tid + it * 256;
                int r = s >> 4, j2 = s & 15;
                cpasync16(dst + (r * BST + j2 * 8) * 2,
                          Bc + (long)r * ldb + (j2 & 7) * 8 + (j2 >> 3) * 4096);
            }
        } else {
            stage_t<BK, BN / 8, BST>(dst, B + (long)c * 64 * ldb, ldb);
        }
    };

    const int nch = K >> 6;
    stage_t<BM, 8, AST>(sb, A, lda);
    stage_B(sb + ABYTES, 0);
    asm volatile("cp.async.commit_group;" ::: "memory");
    stage_t<BM, 8, AST>(sb + STAGE, A + 64, lda);
    stage_B(sb + STAGE + ABYTES, 1);
    asm volatile("cp.async.commit_group;" ::: "memory");

    float acc[FM][FN][4];
    #pragma unroll
    for (int i = 0; i < FM; i++)
        #pragma unroll
        for (int j = 0; j < FN; j++)
            #pragma unroll
            for (int q = 0; q < 4; q++) acc[i][j][q] = 0.f;

    for (int c = 0; c < nch; c++) {
        if (c + 1 < nch) asm volatile("cp.async.wait_group 1;" ::: "memory");
        else             asm volatile("cp.async.wait_group 0;" ::: "memory");
        __syncthreads();

        const uint32_t sA = sb + (c % 3) * STAGE;
        const uint32_t sB = sA + ABYTES;

        #pragma unroll
        for (int kk = 0; kk < 4; kk++) {
            uint32_t af[FM][4], bf[FN][2];
            #pragma unroll
            for (int i = 0; i < FM; i++)
                ldsm_x4(af[i], sA + ((wm + i * 16 + (l & 15)) * AST + kk * 16 + (l >> 4) * 8) * 2);
            #pragma unroll
            for (int p = 0; p < FN / 2; p++) {
                const int bc = (EPI == 3) ? (p == 0 ? wn : 64 + wn) : (wn + p * 16);
                uint32_t r4[4];
                ldsm_x4t(r4, sB + ((kk * 16 + ((l >> 3) & 1) * 8 + (l & 7)) * BST
                                   + bc + ((l >> 4) << 3)) * 2);
                bf[2 * p][0] = r4[0]; bf[2 * p][1] = r4[1];
                bf[2 * p + 1][0] = r4[2]; bf[2 * p + 1][1] = r4[3];
            }
            #pragma unroll
            for (int i = 0; i < FM; i++)
                #pragma unroll
                for (int j = 0; j < FN; j++)
                    mma16816(acc[i][j], af[i], bf[j]);
        }

        if (c + 2 < nch) {
            const uint32_t dA = sb + ((c + 2) % 3) * STAGE;
            stage_t<BM, 8, AST>(dA, A + (long)(c + 2) * 64, lda);
            stage_B(dA + ABYTES, c + 2);
            asm volatile("cp.async.commit_group;" ::: "memory");
        }
    }

    const int tr = l >> 2;
    const int tc = (l & 3) * 2;
    #pragma unroll
    for (int i = 0; i < FM; i++) {
        if (EPI == 3) {
            #pragma unroll
            for (int j = 0; j < 2; j++) {
                const int gm0 = m0 + wm + i * 16 + tr;
                const int gm1 = gm0 + 8;
                const int c = wn + j * 8 + tc;          // block-local out col
                const int gn = n0 + c;
                const float ba0 = bias[gn], ba1 = bias[gn + 1];
                const float bg0 = bias[4096 + gn], bg1 = bias[4096 + gn + 1];
                float* a = acc[i][j];
                float* g = acc[i][j + 2];
                __nv_bfloat16* Cb = (__nv_bfloat16*)Cv;
                *reinterpret_cast<__nv_bfloat162*>(Cb + (long)gm0 * ldc + gn) =
                    __floats2bfloat162_rn((a[0] + ba0) * gelu_exact(g[0] + bg0),
                                          (a[1] + ba1) * gelu_exact(g[1] + bg1));
                *reinterpret_cast<__nv_bfloat162*>(Cb + (long)gm1 * ldc + gn) =
                    __floats2bfloat162_rn((a[2] + ba0) * gelu_exact(g[2] + bg0),
                                          (a[3] + ba1) * gelu_exact(g[3] + bg1));
            }
        } else {
            #pragma unroll
            for (int j = 0; j < FN; j++) {
                const int gm0 = m0 + wm + i * 16 + tr;
                const int gm1 = gm0 + 8;
                const int gn = n0 + wn + j * 8 + tc;
                if (EPI == 0) {
                    __nv_bfloat16* Cb = (__nv_bfloat16*)Cv;
                    float b0 = 0.f, b1 = 0.f;
                    if (bias) { b0 = bias[gn]; b1 = bias[gn + 1]; }
                    *reinterpret_cast<__nv_bfloat162*>(Cb + (long)gm0 * ldc + gn) =
                        __floats2bfloat162_rn(acc[i][j][0] + b0, acc[i][j][1] + b1);
                    *reinterpret_cast<__nv_bfloat162*>(Cb + (long)gm1 * ldc + gn) =
                        __floats2bfloat162_rn(acc[i][j][2] + b0, acc[i][j][3] + b1);
                } else {
                    float* Cf = (float*)Cv;
                    const float b0 = bias[gn], b1 = bias[gn + 1];
                    const float s0 = ls[gn], s1 = ls[gn + 1];
                    float2 v0 = *reinterpret_cast<float2*>(Cf + (long)gm0 * ldc + gn);
                    float2 v1 = *reinterpret_cast<float2*>(Cf + (long)gm1 * ldc + gn);
                    v0.x += (acc[i][j][0] + b0) * s0;
                    v0.y += (acc[i][j][1] + b1) * s1;
                    v1.x += (acc[i][j][2] + b0) * s0;
                    v1.y += (acc[i][j][3] + b1) * s1;
                    *reinterpret_cast<float2*>(Cf + (long)gm0 * ldc + gn) = v0;
                    *reinterpret_cast<float2*>(Cf + (long)gm1 * ldc + gn) = v1;
                }
            }
        }
    }
}

// ---------------- fused flash attention ----------------
__global__ void __launch_bounds__(256) flash_kernel(
    const __nv_bfloat16* __restrict__ qkv, __nv_bfloat16* __restrict__ o) {
    constexpr int QST = 72, KST = 72;
    constexpr int QBYTES = 128 * QST * 2;
    constexpr int KVB = 2 * 64 * KST * 2;
    extern __shared__ __align__(128) char smem[];
    const uint32_t sb = smem_u32(smem);
    const int tid = threadIdx.x, wid = tid >> 5, l = tid & 31;
    const int qt = blockIdx.x, bh = blockIdx.y;
    const int b = bh >> 4, h = bh & 15;
    const __nv_bfloat16* Qg = qkv + (long)b * SEQ * QKV3 + (long)(qt * 128) * QKV3 + h * 64;
    const __nv_bfloat16* Kg = qkv + (long)b * SEQ * QKV3 + 1024 + h * 64;
    const __nv_bfloat16* Vg = qkv + (long)b * SEQ * QKV3 + 2048 + h * 64;

    #pragma unroll
    for (int it = 0; it < 4; it++) {
        int s = tid + it * 256, r = s >> 3, j = s & 7;
        cpasync16(sb + (r * QST + j * 8) * 2, Qg + (long)r * QKV3 + j * 8);
    }
    auto stage_kv = [&](int slot, int c) {
        uint32_t base = sb + QBYTES + slot * KVB;
        const __nv_bfloat16* kg = Kg + (long)(c * 64) * QKV3;
        const __nv_bfloat16* vg = Vg + (long)(c * 64) * QKV3;
        #pragma unroll
        for (int it = 0; it < 2; it++) {
            int s = tid + it * 256, r = s >> 3, j = s & 7;
            cpasync16(base + (r * KST + j * 8) * 2, kg + (long)r * QKV3 + j * 8);
            cpasync16(base + 64 * KST * 2 + (r * KST + j * 8) * 2, vg + (long)r * QKV3 + j * 8);
        }
    };
    stage_kv(0, 0);
    asm volatile("cp.async.commit_group;" ::: "memory");
    stage_kv(1, 1);
    asm volatile("cp.async.commit_group;" ::: "memory");

    float oacc[8][4];
    #pragma unroll
    for (int j = 0; j < 8; j++)
        #pragma unroll
        for (int q = 0; q < 4; q++) oacc[j][q] = 0.f;
    float m0 = -1e30f, m1 = -1e30f, sum0 = 0.f, sum1 = 0.f;
    const int wm = wid * 16;
    constexpr float CS = 0.125f * 1.4426950408889634f;

    for (int c = 0; c < 16; c++) {
        if (c < 15) asm volatile("cp.async.wait_group 1;" ::: "memory");
        else        asm volatile("cp.async.wait_group 0;" ::: "memory");
        __syncthreads();
        const uint32_t sK = sb + QBYTES + (c % 3) * KVB;
        const uint32_t sV = sK + 64 * KST * 2;

        float sacc[8][4];
        #pragma unroll
        for (int j = 0; j < 8; j++)
            #pragma unroll
            for (int q = 0; q < 4; q++) sacc[j][q] = 0.f;
        #pragma unroll
        for (int kk = 0; kk < 4; kk++) {
            uint32_t af[4];
            ldsm_x4(af, sb + ((wm + (l & 15)) * QST + kk * 16 + (l >> 4) * 8) * 2);
            #pragma unroll
            for (int j = 0; j < 8; j += 2) {
                uint32_t bk[4];
                ldsm_x4(bk, sK + ((j * 8 + ((l >> 4) << 3) + (l & 7)) * KST
                                  + kk * 16 + ((l >> 3) & 1) * 8) * 2);
                mma16816(sacc[j], af, bk);
                mma16816(sacc[j + 1], af, bk + 2);
            }
        }
        float mx0 = -1e30f, mx1 = -1e30f;
        #pragma unroll
        for (int j = 0; j < 8; j++) {
            sacc[j][0] *= CS; sacc[j][1] *= CS; sacc[j][2] *= CS; sacc[j][3] *= CS;
            mx0 = fmaxf(mx0, fmaxf(sacc[j][0], sacc[j][1]));
            mx1 = fmaxf(mx1, fmaxf(sacc[j][2], sacc[j][3]));
        }
        mx0 = fmaxf(mx0, __shfl_xor_sync(~0u, mx0, 1));
        mx0 = fmaxf(mx0, __shfl_xor_sync(~0u, mx0, 2));
        mx1 = fmaxf(mx1, __shfl_xor_sync(~0u, mx1, 1));
        mx1 = fmaxf(mx1, __shfl_xor_sync(~0u, mx1, 2));
        const float mn0 = fmaxf(m0, mx0), mn1 = fmaxf(m1, mx1);
        const float al0 = exp2f(m0 - mn0), al1 = exp2f(m1 - mn1);
        m0 = mn0; m1 = mn1;
        sum0 *= al0; sum1 *= al1;
        uint32_t pb[8][2];
        #pragma unroll
        for (int j = 0; j < 8; j++) {
            float p0 = exp2f(sacc[j][0] - mn0), p1 = exp2f(sacc[j][1] - mn0);
            float p2 = exp2f(sacc[j][2] - mn1), p3 = exp2f(sacc[j][3] - mn1);
            sum0 += p0 + p1; sum1 += p2 + p3;
            __nv_bfloat162 t0 = __floats2bfloat162_rn(p0, p1);
            __nv_bfloat162 t1 = __floats2bfloat162_rn(p2, p3);
            pb[j][0] = *reinterpret_cast<uint32_t*>(&t0);
            pb[j][1] = *reinterpret_cast<uint32_t*>(&t1);
            oacc[j][0] *= al0; oacc[j][1] *= al0;
            oacc[j][2] *= al1; oacc[j][3] *= al1;
        }
        #pragma unroll
        for (int kk2 = 0; kk2 < 4; kk2++) {
            uint32_t af2[4] = { pb[2 * kk2][0], pb[2 * kk2][1],
                                pb[2 * kk2 + 1][0], pb[2 * kk2 + 1][1] };
            #pragma unroll
            for (int nj = 0; nj < 8; nj += 2) {
                uint32_t bv[4];
                ldsm_x4t(bv, sV + ((kk2 * 16 + ((l >> 3) & 1) * 8 + (l & 7)) * KST
                                   + nj * 8 + ((l >> 4) << 3)) * 2);
                mma16816(oacc[nj], af2, bv);
                mma16816(oacc[nj + 1], af2, bv + 2);
            }
        }
        if (c + 2 < 16) {
            stage_kv((c + 2) % 3, c + 2);
            asm volatile("cp.async.commit_group;" ::: "memory");
        }
    }
    sum0 += __shfl_xor_sync(~0u, sum0, 1); sum0 += __shfl_xor_sync(~0u, sum0, 2);
    sum1 += __shfl_xor_sync(~0u, sum1, 1); sum1 += __shfl_xor_sync(~0u, sum1, 2);
    const float inv0 = 1.f / sum0, inv1 = 1.f / sum1;
    const int tr = l >> 2, tc = (l & 3) * 2;
    __nv_bfloat16* Ob = o + (long)(b * SEQ + qt * 128 + wm) * DIM + h * 64;
    #pragma unroll
    for (int nj = 0; nj < 8; nj++) {
        *reinterpret_cast<__nv_bfloat162*>(Ob + (long)tr * DIM + nj * 8 + tc) =
            __floats2bfloat162_rn(oacc[nj][0] * inv0, oacc[nj][1] * inv0);
        *reinterpret_cast<__nv_bfloat162*>(Ob + (long)(tr + 8) * DIM + nj * 8 + tc) =
            __floats2bfloat162_rn(oacc[nj][2] * inv1, oacc[nj][3] * inv1);
    }
}

// ---------------- elementwise kernels ----------------
__global__ void convert_kernel(const float4* __restrict__ src,
                               __nv_bfloat16* __restrict__ dst, long n4) {
    long i = (long)blockIdx.x * blockDim.x + threadIdx.x;
    long stride = (long)gridDim.x * blockDim.x;
    __nv_bfloat162* d2 = reinterpret_cast<__nv_bfloat162*>(dst);
    for (; i < n4; i += stride) {
        float4 v = src[i];
        d2[2 * i]     = __floats2bfloat162_rn(v.x, v.y);
        d2[2 * i + 1] = __floats2bfloat162_rn(v.z, v.w);
    }
}

__global__ void copy_kernel(const float4* __restrict__ src, float4* __restrict__ dst) {
    long i = (long)blockIdx.x * blockDim.x + threadIdx.x;
    dst[i] = src[i];
}

__global__ __launch_bounds__(256) void ln_kernel(const float* __restrict__ x,
                                                 const float* __restrict__ w,
                                                 const float* __restrict__ b,
                                                 __nv_bfloat16* __restrict__ out) {
    int row = blockIdx.x;
    int t = threadIdx.x;
    const float4 v = reinterpret_cast<const float4*>(x + (long)row * DIM)[t];
    float s = v.x + v.y + v.z + v.w;
    float q = v.x * v.x + v.y * v.y + v.z * v.z + v.w * v.w;
    __shared__ float rs[8], rq[8];
    #pragma unroll
    for (int o = 16; o; o >>= 1) {
        s += __shfl_xor_sync(0xffffffffu, s, o);
        q += __shfl_xor_sync(0xffffffffu, q, o);
    }
    if ((t & 31) == 0) { rs[t >> 5] = s; rq[t >> 5] = q; }
    __syncthreads();
    float ts = 0.f, tq = 0.f;
    #pragma unroll
    for (int i = 0; i < 8; i++) { ts += rs[i]; tq += rq[i]; }
    float mu = ts * (1.f / DIM);
    float var = tq * (1.f / DIM) - mu * mu;
    float rstd = rsqrtf(var + 1e-5f);
    float4 wv = reinterpret_cast<const float4*>(w)[t];
    float4 bv = reinterpret_cast<const float4*>(b)[t];
    __nv_bfloat162* o2 = reinterpret_cast<__nv_bfloat162*>(out + (long)row * DIM);
    o2[2 * t]     = __floats2bfloat162_rn((v.x - mu) * rstd * wv.x + bv.x,
                                          (v.y - mu) * rstd * wv.y + bv.y);
    o2[2 * t + 1] = __floats2bfloat162_rn((v.z - mu) * rstd * wv.z + bv.z,
                                          (v.w - mu) * rstd * wv.w + bv.w);
}

// ---------------- host ----------------
static void* symAddr(const void* sym) {
    void* p = nullptr;
    cudaGetSymbolAddress(&p, sym);
    return p;
}

extern "C" void kernel_launch(void* const* d_in, const int* in_sizes, int n_in,
                              void* d_out, int out_size) {
    const float* x    = (const float*)d_in[0];
    const float* ln1w = (const float*)d_in[1];
    const float* ln1b = (const float*)d_in[2];
    const float* wqkv = (const float*)d_in[3];
    const float* wout = (const float*)d_in[4];
    const float* bout = (const float*)d_in[5];
    const float* ls1  = (const float*)d_in[6];
    const float* ln2w = (const float*)d_in[7];
    const float* ln2b = (const float*)d_in[8];
    const float* wff1 = (const float*)d_in[9];
    const float* bff1 = (const float*)d_in[10];
    const float* wff2 = (const float*)d_in[11];
    const float* bff2 = (const float*)d_in[12];
    const float* ls2  = (const float*)d_in[13];
    float* out = (float*)d_out;

    __nv_bfloat16* WQ  = (__nv_bfloat16*)symAddr(g_wqkv);
    __nv_bfloat16* WO  = (__nv_bfloat16*)symAddr(g_wout);
    __nv_bfloat16* W1  = (__nv_bfloat16*)symAddr(g_wff1);
    __nv_bfloat16* W2  = (__nv_bfloat16*)symAddr(g_wff2);
    __nv_bfloat16* H   = (__nv_bfloat16*)symAddr(g_h);
    __nv_bfloat16* QKV = (__nv_bfloat16*)symAddr(g_qkv);
    __nv_bfloat16* O   = (__nv_bfloat16*)symAddr(g_o);
    __nv_bfloat16* FFB = (__nv_bfloat16*)symAddr(g_ff);

    constexpr int SM_GEMM = (128 * 72 * 2 + 64 * 136 * 2) * 3;     // 107520
    constexpr int SM_FL   = 128 * 72 * 2 + 3 * (2 * 64 * 72 * 2);  // 73728
    cudaFuncSetAttribute(mma_gemm<128, 128, 0>, cudaFuncAttributeMaxDynamicSharedMemorySize, SM_GEMM);
    cudaFuncSetAttribute(mma_gemm<128, 128, 2>, cudaFuncAttributeMaxDynamicSharedMemorySize, SM_GEMM);
    cudaFuncSetAttribute(mma_gemm<128, 128, 3>, cudaFuncAttributeMaxDynamicSharedMemorySize, SM_GEMM);
    cudaFuncSetAttribute(flash_kernel, cudaFuncAttributeMaxDynamicSharedMemorySize, SM_FL);

    convert_kernel<<<2048, 256>>>((const float4*)wqkv, WQ, (long)DEPTH * DIM * QKV3 / 4);
    convert_kernel<<<2048, 256>>>((const float4*)wout, WO, (long)DEPTH * DIM * DIM / 4);
    convert_kernel<<<2048, 256>>>((const float4*)wff1, W1, (long)DEPTH * DIM * FF2X / 4);
    convert_kernel<<<2048, 256>>>((const float4*)wff2, W2, (long)DEPTH * FF * DIM / 4);

    copy_kernel<<<2048, 256>>>((const float4*)x, (float4*)out);

    for (int l = 0; l < DEPTH; l++) {
        const __nv_bfloat16* Wq = WQ + (long)l * DIM * QKV3;
        const __nv_bfloat16* Wo = WO + (long)l * DIM * DIM;
        const __nv_bfloat16* Wf1 = W1 + (long)l * DIM * FF2X;
        const __nv_bfloat16* Wf2 = W2 + (long)l * FF * DIM;

        ln_kernel<<<TOK, 256>>>(out, ln1w + l * DIM, ln1b + l * DIM, H);

        // QKV = H @ Wq  [2048 x 3072], K=1024
        mma_gemm<128, 128, 0><<<dim3(24, 16), 256, SM_GEMM>>>(
            H, Wq, QKV, nullptr, nullptr, DIM, QKV3, QKV3, DIM);

        // fused attention -> O [2048 x 1024] bf16
        flash_kernel<<<dim3(8, 32), 256, SM_FL>>>(QKV, O);

        // out += (O @ Wo + bout) * ls1  [2048 x 1024], K=1024
        mma_gemm<128, 128, 2><<<dim3(8, 16), 256, SM_GEMM>>>(
            O, Wo, out, bout + l * DIM, ls1 + l * DIM, DIM, DIM, DIM, DIM);

        ln_kernel<<<TOK, 256>>>(out, ln2w + l * DIM, ln2b + l * DIM, H);

        // fused FF1 + GEGLU: FFB[2048 x 4096] = (H@Wf1a + ba) * gelu(H@Wf1g + bg)
        mma_gemm<128, 128, 3><<<dim3(64, 16), 256, SM_GEMM>>>(
            H, Wf1, FFB, bff1 + l * FF2X, nullptr, DIM, FF2X, FF, DIM);

        // out += (FF @ Wf2 + bff2) * ls2  [2048 x 1024], K=4096
        mma_gemm<128, 128, 2><<<dim3(8, 16), 256, SM_GEMM>>>(
            FFB, Wf2, out, bff2 + l * DIM, ls2 + l * DIM, FF, DIM, DIM, FF);
    }
}